// round 1
// baseline (speedup 1.0000x reference)
#include <cuda_runtime.h>
#include <cuda_bf16.h>
#include <math.h>

// Problem constants
#define BATCH 2
#define SEQ   2048
#define DMODEL 2048
#define FF    5632
#define NH    16
#define NKVH  4
#define HD    128
#define KD    (NKVH*HD)      // 512
#define MROWS (BATCH*SEQ)    // 4096

// ---------------- scratch (device globals; no allocation allowed) ----------------
__device__ float g_h   [MROWS * DMODEL];   // rmsnorm1 out
__device__ float g_q   [MROWS * DMODEL];
__device__ float g_k   [MROWS * KD];
__device__ float g_v   [MROWS * KD];
__device__ float g_attn[MROWS * DMODEL];
__device__ float g_x1  [MROWS * DMODEL];   // x + attn@o_w
__device__ float g_h2  [MROWS * DMODEL];   // rmsnorm2 out
__device__ float g_gate[MROWS * FF];
__device__ float g_act [MROWS * FF];       // silu(gate)*up

// ---------------- RMSNorm: one block per row, D=2048 ----------------
__global__ void __launch_bounds__(256) rmsnorm_kernel(
    const float* __restrict__ x, const float* __restrict__ w, float* __restrict__ out)
{
    int row = blockIdx.x;
    int tid = threadIdx.x;
    const float4* xr = (const float4*)(x + (size_t)row * DMODEL);
    const float4* wr = (const float4*)w;
    float4 v0 = xr[tid];
    float4 v1 = xr[tid + 256];
    float ss = v0.x*v0.x + v0.y*v0.y + v0.z*v0.z + v0.w*v0.w
             + v1.x*v1.x + v1.y*v1.y + v1.z*v1.z + v1.w*v1.w;
    #pragma unroll
    for (int o = 16; o > 0; o >>= 1) ss += __shfl_xor_sync(0xffffffffu, ss, o);
    __shared__ float red[8];
    if ((tid & 31) == 0) red[tid >> 5] = ss;
    __syncthreads();
    float tot = red[0]+red[1]+red[2]+red[3]+red[4]+red[5]+red[6]+red[7];
    float inv = rsqrtf(tot / (float)DMODEL + 1e-6f);
    float4 w0 = wr[tid], w1 = wr[tid + 256];
    float4 o0, o1;
    o0.x = v0.x*inv*w0.x; o0.y = v0.y*inv*w0.y; o0.z = v0.z*inv*w0.z; o0.w = v0.w*inv*w0.w;
    o1.x = v1.x*inv*w1.x; o1.y = v1.y*inv*w1.y; o1.z = v1.z*inv*w1.z; o1.w = v1.w*inv*w1.w;
    float4* outr = (float4*)(out + (size_t)row * DMODEL);
    outr[tid] = o0; outr[tid + 256] = o1;
}

// ---------------- SGEMM (NT): C[M,N] = A[M,K] @ W[N,K]^T  (+bias / +res / swiglu) ----
// 128x128x16 tile, 256 threads, 8x8 per thread, cols mapped tx + 16*j for coalescing.
__global__ void __launch_bounds__(256, 2) sgemm_nt(
    const float* __restrict__ A, const float* __restrict__ W,
    const float* __restrict__ bias, const float* __restrict__ res,
    const float* __restrict__ gate, float* __restrict__ C,
    int M, int N, int K)
{
    __shared__ float As[16][128];
    __shared__ float Bs[16][128];
    int tid = threadIdx.x;
    int m0 = blockIdx.y * 128, n0 = blockIdx.x * 128;
    int tx = tid & 15, ty = tid >> 4;

    float acc[8][8];
    #pragma unroll
    for (int i = 0; i < 8; i++)
        #pragma unroll
        for (int j = 0; j < 8; j++) acc[i][j] = 0.f;

    int lr = tid >> 2;            // 0..63
    int lc = (tid & 3) << 2;      // 0,4,8,12
    const float* Ap = A + (size_t)(m0 + lr) * K + lc;
    const float* Bp = W + (size_t)(n0 + lr) * K + lc;
    const size_t rstep = (size_t)64 * K;

    for (int k0 = 0; k0 < K; k0 += 16) {
        float4 a0 = *(const float4*)(Ap + k0);
        float4 a1 = *(const float4*)(Ap + rstep + k0);
        float4 b0 = *(const float4*)(Bp + k0);
        float4 b1 = *(const float4*)(Bp + rstep + k0);
        As[lc+0][lr] = a0.x; As[lc+1][lr] = a0.y; As[lc+2][lr] = a0.z; As[lc+3][lr] = a0.w;
        As[lc+0][lr+64] = a1.x; As[lc+1][lr+64] = a1.y; As[lc+2][lr+64] = a1.z; As[lc+3][lr+64] = a1.w;
        Bs[lc+0][lr] = b0.x; Bs[lc+1][lr] = b0.y; Bs[lc+2][lr] = b0.z; Bs[lc+3][lr] = b0.w;
        Bs[lc+0][lr+64] = b1.x; Bs[lc+1][lr+64] = b1.y; Bs[lc+2][lr+64] = b1.z; Bs[lc+3][lr+64] = b1.w;
        __syncthreads();
        #pragma unroll
        for (int kk = 0; kk < 16; kk++) {
            float ar[8], br[8];
            *(float4*)&ar[0] = *(const float4*)&As[kk][ty*8];
            *(float4*)&ar[4] = *(const float4*)&As[kk][ty*8 + 4];
            #pragma unroll
            for (int j = 0; j < 8; j++) br[j] = Bs[kk][tx + 16*j];
            #pragma unroll
            for (int i = 0; i < 8; i++)
                #pragma unroll
                for (int j = 0; j < 8; j++) acc[i][j] += ar[i] * br[j];
        }
        __syncthreads();
    }

    #pragma unroll
    for (int i = 0; i < 8; i++) {
        int r = m0 + ty*8 + i;
        #pragma unroll
        for (int j = 0; j < 8; j++) {
            int c = n0 + tx + 16*j;
            float v = acc[i][j];
            if (bias) v += bias[c];
            size_t idx = (size_t)r * N + c;
            if (gate) { float g = gate[idx]; v = v * (g / (1.f + __expf(-g))); }
            if (res)  v += res[idx];
            C[idx] = v;
        }
    }
}

// ---------------- Flash attention (causal, GQA rep=4), fp32 ----------------
// Block: 64 query rows for one (b,h). 256 threads. Online softmax.
#define FA_SMEM_FLOATS (64*129*3 + 64*65 + 64*3)
#define FA_SMEM_BYTES  (FA_SMEM_FLOATS * 4)

__global__ void __launch_bounds__(256) flash_attn_kernel(
    const float* __restrict__ Q, const float* __restrict__ Kb,
    const float* __restrict__ Vb, float* __restrict__ O)
{
    extern __shared__ float sm[];
    float* Qs = sm;                    // [64][129]
    float* Ks = Qs + 64*129;           // [64][129]
    float* Vs = Ks + 64*129;           // [64][129]
    float* Ss = Vs + 64*129;           // [64][65]
    float* ms = Ss + 64*65;            // [64]
    float* ls = ms + 64;               // [64]
    float* cs = ls + 64;               // [64]

    int qt = blockIdx.x;               // 0..31
    int bh = blockIdx.y;               // 0..31
    int b = bh >> 4, h = bh & 15, kvh = h & 3;
    int q0 = qt * 64;
    int tid = threadIdx.x, tx = tid & 15, ty = tid >> 4;
    const float scale = 0.08838834764831845f;  // 1/sqrt(128)

    // load Q tile (scale folded in)
    for (int u = tid; u < 64*32; u += 256) {
        int r = u >> 5, c4 = (u & 31) << 2;
        float4 qv = *(const float4*)(Q + (size_t)(b*SEQ + q0 + r) * DMODEL + h*HD + c4);
        Qs[r*129 + c4+0] = qv.x * scale;
        Qs[r*129 + c4+1] = qv.y * scale;
        Qs[r*129 + c4+2] = qv.z * scale;
        Qs[r*129 + c4+3] = qv.w * scale;
    }
    if (tid < 64) { ms[tid] = -INFINITY; ls[tid] = 0.f; }

    float o[4][8];
    #pragma unroll
    for (int i = 0; i < 4; i++)
        #pragma unroll
        for (int j = 0; j < 8; j++) o[i][j] = 0.f;

    for (int kt = 0; kt <= qt; kt++) {
        int k0 = kt * 64;
        __syncthreads();   // previous iter done with Ks/Vs (and Q ready on iter 0)
        for (int u = tid; u < 64*32; u += 256) {
            int r = u >> 5, c4 = (u & 31) << 2;
            size_t base = (size_t)(b*SEQ + k0 + r) * KD + kvh*HD + c4;
            float4 kv = *(const float4*)(Kb + base);
            float4 vv = *(const float4*)(Vb + base);
            Ks[r*129 + c4+0] = kv.x; Ks[r*129 + c4+1] = kv.y;
            Ks[r*129 + c4+2] = kv.z; Ks[r*129 + c4+3] = kv.w;
            Vs[r*129 + c4+0] = vv.x; Vs[r*129 + c4+1] = vv.y;
            Vs[r*129 + c4+2] = vv.z; Vs[r*129 + c4+3] = vv.w;
        }
        __syncthreads();

        // S = Qs @ Ks^T   (rows ty*4+i, cols tx+16*jj)
        float s[4][4];
        #pragma unroll
        for (int i = 0; i < 4; i++)
            #pragma unroll
            for (int jj = 0; jj < 4; jj++) s[i][jj] = 0.f;
        for (int d = 0; d < 128; d++) {
            float qr[4], kr[4];
            #pragma unroll
            for (int i = 0; i < 4; i++) qr[i] = Qs[(ty*4+i)*129 + d];
            #pragma unroll
            for (int jj = 0; jj < 4; jj++) kr[jj] = Ks[(tx+16*jj)*129 + d];
            #pragma unroll
            for (int i = 0; i < 4; i++)
                #pragma unroll
                for (int jj = 0; jj < 4; jj++) s[i][jj] += qr[i] * kr[jj];
        }
        #pragma unroll
        for (int i = 0; i < 4; i++)
            #pragma unroll
            for (int jj = 0; jj < 4; jj++)
                Ss[(ty*4+i)*65 + tx + 16*jj] = s[i][jj];
        __syncthreads();

        // online softmax row stats (one thread per row)
        if (tid < 64) {
            int r = tid;
            int cmax = (kt == qt) ? (r + 1) : 64;   // causal: k0+c <= q0+r on diagonal
            float mprev = ms[r], mx = mprev;
            for (int c = 0; c < cmax; c++) mx = fmaxf(mx, Ss[r*65 + c]);
            float corr = __expf(mprev - mx);
            float sum = 0.f;
            for (int c = 0; c < 64; c++) {
                float p = (c < cmax) ? __expf(Ss[r*65 + c] - mx) : 0.f;
                Ss[r*65 + c] = p;
                sum += p;
            }
            ls[r] = ls[r] * corr + sum;
            ms[r] = mx;
            cs[r] = corr;
        }
        __syncthreads();

        // rescale accumulators, then O += P @ V
        #pragma unroll
        for (int i = 0; i < 4; i++) {
            float co = cs[ty*4 + i];
            #pragma unroll
            for (int j = 0; j < 8; j++) o[i][j] *= co;
        }
        for (int kk = 0; kk < 64; kk++) {
            float p[4], vv[8];
            #pragma unroll
            for (int i = 0; i < 4; i++) p[i] = Ss[(ty*4+i)*65 + kk];
            #pragma unroll
            for (int j = 0; j < 8; j++) vv[j] = Vs[kk*129 + tx + 16*j];
            #pragma unroll
            for (int i = 0; i < 4; i++)
                #pragma unroll
                for (int j = 0; j < 8; j++) o[i][j] += p[i] * vv[j];
        }
    }

    // write out normalized
    #pragma unroll
    for (int i = 0; i < 4; i++) {
        int r = ty*4 + i;
        float inv = 1.f / ls[r];
        #pragma unroll
        for (int j = 0; j < 8; j++) {
            O[(size_t)(b*SEQ + q0 + r) * DMODEL + h*HD + tx + 16*j] = o[i][j] * inv;
        }
    }
}

// ---------------- host launcher ----------------
extern "C" void kernel_launch(void* const* d_in, const int* in_sizes, int n_in,
                              void* d_out, int out_size)
{
    const float* x      = (const float*)d_in[0];
    const float* ln1_w  = (const float*)d_in[1];
    const float* q_w    = (const float*)d_in[2];
    const float* q_b    = (const float*)d_in[3];
    const float* k_w    = (const float*)d_in[4];
    const float* k_b    = (const float*)d_in[5];
    const float* v_w    = (const float*)d_in[6];
    const float* v_b    = (const float*)d_in[7];
    const float* o_w    = (const float*)d_in[8];
    const float* ln2_w  = (const float*)d_in[9];
    const float* gate_w = (const float*)d_in[10];
    const float* up_w   = (const float*)d_in[11];
    const float* down_w = (const float*)d_in[12];
    float* out = (float*)d_out;

    float *h, *q, *k, *v, *attn, *x1, *h2, *gate, *act;
    cudaGetSymbolAddress((void**)&h,    g_h);
    cudaGetSymbolAddress((void**)&q,    g_q);
    cudaGetSymbolAddress((void**)&k,    g_k);
    cudaGetSymbolAddress((void**)&v,    g_v);
    cudaGetSymbolAddress((void**)&attn, g_attn);
    cudaGetSymbolAddress((void**)&x1,   g_x1);
    cudaGetSymbolAddress((void**)&h2,   g_h2);
    cudaGetSymbolAddress((void**)&gate, g_gate);
    cudaGetSymbolAddress((void**)&act,  g_act);

    cudaFuncSetAttribute(flash_attn_kernel,
                         cudaFuncAttributeMaxDynamicSharedMemorySize, FA_SMEM_BYTES);

    // 1) h = rmsnorm(x, ln1_w)
    rmsnorm_kernel<<<MROWS, 256>>>(x, ln1_w, h);

    // 2) q/k/v projections
    sgemm_nt<<<dim3(DMODEL/128, MROWS/128), 256>>>(h, q_w, q_b, nullptr, nullptr, q,
                                                   MROWS, DMODEL, DMODEL);
    sgemm_nt<<<dim3(KD/128, MROWS/128), 256>>>(h, k_w, k_b, nullptr, nullptr, k,
                                               MROWS, KD, DMODEL);
    sgemm_nt<<<dim3(KD/128, MROWS/128), 256>>>(h, v_w, v_b, nullptr, nullptr, v,
                                               MROWS, KD, DMODEL);

    // 3) attention
    flash_attn_kernel<<<dim3(SEQ/64, BATCH*NH), 256, FA_SMEM_BYTES>>>(q, k, v, attn);

    // 4) x1 = x + attn @ o_w^T
    sgemm_nt<<<dim3(DMODEL/128, MROWS/128), 256>>>(attn, o_w, nullptr, x, nullptr, x1,
                                                   MROWS, DMODEL, DMODEL);

    // 5) h2 = rmsnorm(x1, ln2_w)
    rmsnorm_kernel<<<MROWS, 256>>>(x1, ln2_w, h2);

    // 6) gate = h2 @ gate_w^T ; act = silu(gate) * (h2 @ up_w^T)
    sgemm_nt<<<dim3(FF/128, MROWS/128), 256>>>(h2, gate_w, nullptr, nullptr, nullptr, gate,
                                               MROWS, FF, DMODEL);
    sgemm_nt<<<dim3(FF/128, MROWS/128), 256>>>(h2, up_w, nullptr, nullptr, gate, act,
                                               MROWS, FF, DMODEL);

    // 7) out = x1 + act @ down_w^T
    sgemm_nt<<<dim3(DMODEL/128, MROWS/128), 256>>>(act, down_w, nullptr, x1, nullptr, out,
                                                   MROWS, DMODEL, FF);
}

// round 6
// speedup vs baseline: 2.3211x; 2.3211x over previous
#include <cuda_runtime.h>
#include <cuda_bf16.h>
#include <math.h>
#include <stdint.h>

// Problem constants
#define BATCH 2
#define SEQ   2048
#define DMODEL 2048
#define FF    5632
#define NH    16
#define NKVH  4
#define HD    128
#define KD    (NKVH*HD)      // 512
#define MROWS (BATCH*SEQ)    // 4096

// ---------------- scratch (device globals; no allocation allowed) ----------------
__device__ float g_h   [MROWS * DMODEL];   // rmsnorm1 out
__device__ float g_q   [MROWS * DMODEL];
__device__ float g_k   [MROWS * KD];
__device__ float g_v   [MROWS * KD];
__device__ float g_attn[MROWS * DMODEL];
__device__ float g_x1  [MROWS * DMODEL];   // x + attn@o_w
__device__ float g_h2  [MROWS * DMODEL];   // rmsnorm2 out
__device__ float g_gate[MROWS * FF];
__device__ float g_act [MROWS * FF];       // silu(gate)*up

// ---------------- RMSNorm: one block per row, D=2048 ----------------
__global__ void __launch_bounds__(256) rmsnorm_kernel(
    const float* __restrict__ x, const float* __restrict__ w, float* __restrict__ out)
{
    int row = blockIdx.x;
    int tid = threadIdx.x;
    const float4* xr = (const float4*)(x + (size_t)row * DMODEL);
    const float4* wr = (const float4*)w;
    float4 v0 = xr[tid];
    float4 v1 = xr[tid + 256];
    float ss = v0.x*v0.x + v0.y*v0.y + v0.z*v0.z + v0.w*v0.w
             + v1.x*v1.x + v1.y*v1.y + v1.z*v1.z + v1.w*v1.w;
    #pragma unroll
    for (int o = 16; o > 0; o >>= 1) ss += __shfl_xor_sync(0xffffffffu, ss, o);
    __shared__ float red[8];
    if ((tid & 31) == 0) red[tid >> 5] = ss;
    __syncthreads();
    float tot = red[0]+red[1]+red[2]+red[3]+red[4]+red[5]+red[6]+red[7];
    float inv = rsqrtf(tot / (float)DMODEL + 1e-6f);
    float4 w0 = wr[tid], w1 = wr[tid + 256];
    float4 o0, o1;
    o0.x = v0.x*inv*w0.x; o0.y = v0.y*inv*w0.y; o0.z = v0.z*inv*w0.z; o0.w = v0.w*inv*w0.w;
    o1.x = v1.x*inv*w1.x; o1.y = v1.y*inv*w1.y; o1.z = v1.z*inv*w1.z; o1.w = v1.w*inv*w1.w;
    float4* outr = (float4*)(out + (size_t)row * DMODEL);
    outr[tid] = o0; outr[tid + 256] = o1;
}

// ---------------- TF32 tensor-core GEMM (NT): C[M,N] = A[M,K] @ W[N,K]^T ----------
// 128x128x32 block tile, 256 threads, 8 warps (4m x 2n), warp tile 32x64.
// mma.sync.m16n8k8.tf32, fp32 accumulate. Smem row stride 36 -> conflict-free frags.

__device__ __forceinline__ uint32_t f2tf32(float f) {
    uint32_t u;
    asm("cvt.rna.tf32.f32 %0, %1;" : "=r"(u) : "f"(f));
    return u;
}

__device__ __forceinline__ void mma_tf32(float c[4], const uint32_t a[4], const uint32_t b[2]) {
    asm volatile(
        "mma.sync.aligned.m16n8k8.row.col.f32.tf32.tf32.f32 "
        "{%0,%1,%2,%3}, {%4,%5,%6,%7}, {%8,%9}, {%0,%1,%2,%3};"
        : "+f"(c[0]), "+f"(c[1]), "+f"(c[2]), "+f"(c[3])
        : "r"(a[0]), "r"(a[1]), "r"(a[2]), "r"(a[3]), "r"(b[0]), "r"(b[1]));
}

#define TSTRIDE 36   // 32 k-floats + pad 4: frag banks = (4g + t4) % 32, conflict-free

__global__ void __launch_bounds__(256, 2) tgemm_nt(
    const float* __restrict__ A, const float* __restrict__ W,
    const float* __restrict__ bias, const float* __restrict__ res,
    const float* __restrict__ gate, float* __restrict__ C,
    int M, int N, int K)
{
    __shared__ uint32_t As[128 * TSTRIDE];
    __shared__ uint32_t Bs[128 * TSTRIDE];

    int tid = threadIdx.x;
    int m0 = blockIdx.y * 128, n0 = blockIdx.x * 128;
    int lane = tid & 31, wid = tid >> 5;
    int warp_m = wid >> 1;          // 0..3  (32 rows each)
    int warp_n = wid & 1;           // 0..1  (64 cols each)
    int g = lane >> 2, t4 = lane & 3;

    float c[2][8][4];
    #pragma unroll
    for (int mt = 0; mt < 2; mt++)
        #pragma unroll
        for (int nt = 0; nt < 8; nt++)
            #pragma unroll
            for (int i = 0; i < 4; i++) c[mt][nt][i] = 0.f;

    const float* Abase = A + (size_t)m0 * K;
    const float* Wbase = W + (size_t)n0 * K;

    for (int k0 = 0; k0 < K; k0 += 32) {
        // load 128x32 tiles of A and W, convert to tf32, store [row][k] stride 36
        #pragma unroll
        for (int i = 0; i < 4; i++) {
            int u = tid + i * 256;           // 0..1023
            int row = u >> 3;
            int kq = (u & 7) << 2;
            float4 av = *(const float4*)(Abase + (size_t)row * K + k0 + kq);
            float4 bv = *(const float4*)(Wbase + (size_t)row * K + k0 + kq);
            uint4 at, bt;
            at.x = f2tf32(av.x); at.y = f2tf32(av.y); at.z = f2tf32(av.z); at.w = f2tf32(av.w);
            bt.x = f2tf32(bv.x); bt.y = f2tf32(bv.y); bt.z = f2tf32(bv.z); bt.w = f2tf32(bv.w);
            *(uint4*)&As[row * TSTRIDE + kq] = at;
            *(uint4*)&Bs[row * TSTRIDE + kq] = bt;
        }
        __syncthreads();

        #pragma unroll
        for (int kk = 0; kk < 4; kk++) {
            int kb = kk * 8 + t4;
            uint32_t a[2][4], b[8][2];
            #pragma unroll
            for (int mt = 0; mt < 2; mt++) {
                int r = warp_m * 32 + mt * 16 + g;
                a[mt][0] = As[r * TSTRIDE + kb];
                a[mt][1] = As[(r + 8) * TSTRIDE + kb];
                a[mt][2] = As[r * TSTRIDE + kb + 4];
                a[mt][3] = As[(r + 8) * TSTRIDE + kb + 4];
            }
            #pragma unroll
            for (int nt = 0; nt < 8; nt++) {
                int cn = warp_n * 64 + nt * 8 + g;
                b[nt][0] = Bs[cn * TSTRIDE + kb];
                b[nt][1] = Bs[cn * TSTRIDE + kb + 4];
            }
            #pragma unroll
            for (int mt = 0; mt < 2; mt++)
                #pragma unroll
                for (int nt = 0; nt < 8; nt++)
                    mma_tf32(c[mt][nt], a[mt], b[nt]);
        }
        __syncthreads();
    }

    // epilogue: c0,c1 -> (row g, cols 2*t4, 2*t4+1); c2,c3 -> row g+8
    #pragma unroll
    for (int mt = 0; mt < 2; mt++) {
        int r0 = m0 + warp_m * 32 + mt * 16 + g;
        #pragma unroll
        for (int nt = 0; nt < 8; nt++) {
            int cl = n0 + warp_n * 64 + nt * 8 + t4 * 2;
            #pragma unroll
            for (int half = 0; half < 2; half++) {
                int r = r0 + half * 8;
                float v0 = c[mt][nt][half * 2 + 0];
                float v1 = c[mt][nt][half * 2 + 1];
                if (bias) { v0 += bias[cl]; v1 += bias[cl + 1]; }
                size_t idx = (size_t)r * N + cl;
                if (gate) {
                    float g0 = gate[idx], g1 = gate[idx + 1];
                    v0 *= g0 / (1.f + __expf(-g0));
                    v1 *= g1 / (1.f + __expf(-g1));
                }
                if (res) { v0 += res[idx]; v1 += res[idx + 1]; }
                float2 p; p.x = v0; p.y = v1;
                *(float2*)(C + idx) = p;
            }
        }
    }
}

// ---------------- Flash attention (causal, GQA rep=4), fp32 ----------------
// Block: 64 query rows for one (b,h). 256 threads. Online softmax.
#define FA_SMEM_FLOATS (64*129*3 + 64*65 + 64*3)
#define FA_SMEM_BYTES  (FA_SMEM_FLOATS * 4)

__global__ void __launch_bounds__(256) flash_attn_kernel(
    const float* __restrict__ Q, const float* __restrict__ Kb,
    const float* __restrict__ Vb, float* __restrict__ O)
{
    extern __shared__ float sm[];
    float* Qs = sm;                    // [64][129]
    float* Ks = Qs + 64*129;           // [64][129]
    float* Vs = Ks + 64*129;           // [64][129]
    float* Ss = Vs + 64*129;           // [64][65]
    float* ms = Ss + 64*65;            // [64]
    float* ls = ms + 64;               // [64]
    float* cs = ls + 64;               // [64]

    int qt = blockIdx.x;               // 0..31
    int bh = blockIdx.y;               // 0..31
    int b = bh >> 4, h = bh & 15, kvh = h & 3;
    int q0 = qt * 64;
    int tid = threadIdx.x, tx = tid & 15, ty = tid >> 4;
    const float scale = 0.08838834764831845f;  // 1/sqrt(128)

    for (int u = tid; u < 64*32; u += 256) {
        int r = u >> 5, c4 = (u & 31) << 2;
        float4 qv = *(const float4*)(Q + (size_t)(b*SEQ + q0 + r) * DMODEL + h*HD + c4);
        Qs[r*129 + c4+0] = qv.x * scale;
        Qs[r*129 + c4+1] = qv.y * scale;
        Qs[r*129 + c4+2] = qv.z * scale;
        Qs[r*129 + c4+3] = qv.w * scale;
    }
    if (tid < 64) { ms[tid] = -INFINITY; ls[tid] = 0.f; }

    float o[4][8];
    #pragma unroll
    for (int i = 0; i < 4; i++)
        #pragma unroll
        for (int j = 0; j < 8; j++) o[i][j] = 0.f;

    for (int kt = 0; kt <= qt; kt++) {
        int k0 = kt * 64;
        __syncthreads();
        for (int u = tid; u < 64*32; u += 256) {
            int r = u >> 5, c4 = (u & 31) << 2;
            size_t base = (size_t)(b*SEQ + k0 + r) * KD + kvh*HD + c4;
            float4 kv = *(const float4*)(Kb + base);
            float4 vv = *(const float4*)(Vb + base);
            Ks[r*129 + c4+0] = kv.x; Ks[r*129 + c4+1] = kv.y;
            Ks[r*129 + c4+2] = kv.z; Ks[r*129 + c4+3] = kv.w;
            Vs[r*129 + c4+0] = vv.x; Vs[r*129 + c4+1] = vv.y;
            Vs[r*129 + c4+2] = vv.z; Vs[r*129 + c4+3] = vv.w;
        }
        __syncthreads();

        float s[4][4];
        #pragma unroll
        for (int i = 0; i < 4; i++)
            #pragma unroll
            for (int jj = 0; jj < 4; jj++) s[i][jj] = 0.f;
        for (int d = 0; d < 128; d++) {
            float qr[4], kr[4];
            #pragma unroll
            for (int i = 0; i < 4; i++) qr[i] = Qs[(ty*4+i)*129 + d];
            #pragma unroll
            for (int jj = 0; jj < 4; jj++) kr[jj] = Ks[(tx+16*jj)*129 + d];
            #pragma unroll
            for (int i = 0; i < 4; i++)
                #pragma unroll
                for (int jj = 0; jj < 4; jj++) s[i][jj] += qr[i] * kr[jj];
        }
        #pragma unroll
        for (int i = 0; i < 4; i++)
            #pragma unroll
            for (int jj = 0; jj < 4; jj++)
                Ss[(ty*4+i)*65 + tx + 16*jj] = s[i][jj];
        __syncthreads();

        if (tid < 64) {
            int r = tid;
            int cmax = (kt == qt) ? (r + 1) : 64;
            float mprev = ms[r], mx = mprev;
            for (int c = 0; c < cmax; c++) mx = fmaxf(mx, Ss[r*65 + c]);
            float corr = __expf(mprev - mx);
            float sum = 0.f;
            for (int c = 0; c < 64; c++) {
                float p = (c < cmax) ? __expf(Ss[r*65 + c] - mx) : 0.f;
                Ss[r*65 + c] = p;
                sum += p;
            }
            ls[r] = ls[r] * corr + sum;
            ms[r] = mx;
            cs[r] = corr;
        }
        __syncthreads();

        #pragma unroll
        for (int i = 0; i < 4; i++) {
            float co = cs[ty*4 + i];
            #pragma unroll
            for (int j = 0; j < 8; j++) o[i][j] *= co;
        }
        for (int kk = 0; kk < 64; kk++) {
            float p[4], vv[8];
            #pragma unroll
            for (int i = 0; i < 4; i++) p[i] = Ss[(ty*4+i)*65 + kk];
            #pragma unroll
            for (int j = 0; j < 8; j++) vv[j] = Vs[kk*129 + tx + 16*j];
            #pragma unroll
            for (int i = 0; i < 4; i++)
                #pragma unroll
                for (int j = 0; j < 8; j++) o[i][j] += p[i] * vv[j];
        }
    }

    #pragma unroll
    for (int i = 0; i < 4; i++) {
        int r = ty*4 + i;
        float inv = 1.f / ls[r];
        #pragma unroll
        for (int j = 0; j < 8; j++) {
            O[(size_t)(b*SEQ + q0 + r) * DMODEL + h*HD + tx + 16*j] = o[i][j] * inv;
        }
    }
}

// ---------------- host launcher ----------------
extern "C" void kernel_launch(void* const* d_in, const int* in_sizes, int n_in,
                              void* d_out, int out_size)
{
    const float* x      = (const float*)d_in[0];
    const float* ln1_w  = (const float*)d_in[1];
    const float* q_w    = (const float*)d_in[2];
    const float* q_b    = (const float*)d_in[3];
    const float* k_w    = (const float*)d_in[4];
    const float* k_b    = (const float*)d_in[5];
    const float* v_w    = (const float*)d_in[6];
    const float* v_b    = (const float*)d_in[7];
    const float* o_w    = (const float*)d_in[8];
    const float* ln2_w  = (const float*)d_in[9];
    const float* gate_w = (const float*)d_in[10];
    const float* up_w   = (const float*)d_in[11];
    const float* down_w = (const float*)d_in[12];
    float* out = (float*)d_out;

    float *h, *q, *k, *v, *attn, *x1, *h2, *gate, *act;
    cudaGetSymbolAddress((void**)&h,    g_h);
    cudaGetSymbolAddress((void**)&q,    g_q);
    cudaGetSymbolAddress((void**)&k,    g_k);
    cudaGetSymbolAddress((void**)&v,    g_v);
    cudaGetSymbolAddress((void**)&attn, g_attn);
    cudaGetSymbolAddress((void**)&x1,   g_x1);
    cudaGetSymbolAddress((void**)&h2,   g_h2);
    cudaGetSymbolAddress((void**)&gate, g_gate);
    cudaGetSymbolAddress((void**)&act,  g_act);

    cudaFuncSetAttribute(flash_attn_kernel,
                         cudaFuncAttributeMaxDynamicSharedMemorySize, FA_SMEM_BYTES);

    // 1) h = rmsnorm(x, ln1_w)
    rmsnorm_kernel<<<MROWS, 256>>>(x, ln1_w, h);

    // 2) q/k/v projections (tf32 tensor cores)
    tgemm_nt<<<dim3(DMODEL/128, MROWS/128), 256>>>(h, q_w, q_b, nullptr, nullptr, q,
                                                   MROWS, DMODEL, DMODEL);
    tgemm_nt<<<dim3(KD/128, MROWS/128), 256>>>(h, k_w, k_b, nullptr, nullptr, k,
                                               MROWS, KD, DMODEL);
    tgemm_nt<<<dim3(KD/128, MROWS/128), 256>>>(h, v_w, v_b, nullptr, nullptr, v,
                                               MROWS, KD, DMODEL);

    // 3) attention
    flash_attn_kernel<<<dim3(SEQ/64, BATCH*NH), 256, FA_SMEM_BYTES>>>(q, k, v, attn);

    // 4) x1 = x + attn @ o_w^T
    tgemm_nt<<<dim3(DMODEL/128, MROWS/128), 256>>>(attn, o_w, nullptr, x, nullptr, x1,
                                                   MROWS, DMODEL, DMODEL);

    // 5) h2 = rmsnorm(x1, ln2_w)
    rmsnorm_kernel<<<MROWS, 256>>>(x1, ln2_w, h2);

    // 6) gate = h2 @ gate_w^T ; act = silu(gate) * (h2 @ up_w^T)
    tgemm_nt<<<dim3(FF/128, MROWS/128), 256>>>(h2, gate_w, nullptr, nullptr, nullptr, gate,
                                               MROWS, FF, DMODEL);
    tgemm_nt<<<dim3(FF/128, MROWS/128), 256>>>(h2, up_w, nullptr, nullptr, gate, act,
                                               MROWS, FF, DMODEL);

    // 7) out = x1 + act @ down_w^T
    tgemm_nt<<<dim3(DMODEL/128, MROWS/128), 256>>>(act, down_w, nullptr, x1, nullptr, out,
                                                   MROWS, DMODEL, FF);
}

// round 7
// speedup vs baseline: 2.3542x; 1.0143x over previous
#include <cuda_runtime.h>
#include <math.h>
#include <stdint.h>

// Problem constants
#define BATCH 2
#define SEQ   2048
#define DMODEL 2048
#define FF    5632
#define NH    16
#define NKVH  4
#define HD    128
#define KD    (NKVH*HD)      // 512
#define MROWS (BATCH*SEQ)    // 4096

// ---------------- scratch (device globals) ----------------
__device__ float g_h   [MROWS * DMODEL];
__device__ float g_q   [MROWS * DMODEL];
__device__ float g_k   [MROWS * KD];
__device__ float g_vt  [KD * MROWS];      // V stored TRANSPOSED: [kv_dim][row]
__device__ float g_attn[MROWS * DMODEL];
__device__ float g_x1  [MROWS * DMODEL];
__device__ float g_h2  [MROWS * DMODEL];
__device__ float g_gate[MROWS * FF];
__device__ float g_act [MROWS * FF];

__device__ __forceinline__ uint32_t f2tf32(float f) {
    uint32_t u; asm("cvt.rna.tf32.f32 %0, %1;" : "=r"(u) : "f"(f)); return u;
}
__device__ __forceinline__ void mma_tf32(float* c,
    uint32_t a0, uint32_t a1, uint32_t a2, uint32_t a3, uint32_t b0, uint32_t b1)
{
    asm volatile("mma.sync.aligned.m16n8k8.row.col.f32.tf32.tf32.f32 "
        "{%0,%1,%2,%3}, {%4,%5,%6,%7}, {%8,%9}, {%0,%1,%2,%3};"
        : "+f"(c[0]), "+f"(c[1]), "+f"(c[2]), "+f"(c[3])
        : "r"(a0), "r"(a1), "r"(a2), "r"(a3), "r"(b0), "r"(b1));
}

// ---------------- RMSNorm ----------------
__global__ void __launch_bounds__(256) rmsnorm_kernel(
    const float* __restrict__ x, const float* __restrict__ w, float* __restrict__ out)
{
    int row = blockIdx.x;
    int tid = threadIdx.x;
    const float4* xr = (const float4*)(x + (size_t)row * DMODEL);
    const float4* wr = (const float4*)w;
    float4 v0 = xr[tid];
    float4 v1 = xr[tid + 256];
    float ss = v0.x*v0.x + v0.y*v0.y + v0.z*v0.z + v0.w*v0.w
             + v1.x*v1.x + v1.y*v1.y + v1.z*v1.z + v1.w*v1.w;
    #pragma unroll
    for (int o = 16; o > 0; o >>= 1) ss += __shfl_xor_sync(0xffffffffu, ss, o);
    __shared__ float red[8];
    if ((tid & 31) == 0) red[tid >> 5] = ss;
    __syncthreads();
    float tot = red[0]+red[1]+red[2]+red[3]+red[4]+red[5]+red[6]+red[7];
    float inv = rsqrtf(tot / (float)DMODEL + 1e-6f);
    float4 w0 = wr[tid], w1 = wr[tid + 256];
    float4 o0, o1;
    o0.x = v0.x*inv*w0.x; o0.y = v0.y*inv*w0.y; o0.z = v0.z*inv*w0.z; o0.w = v0.w*inv*w0.w;
    o1.x = v1.x*inv*w1.x; o1.y = v1.y*inv*w1.y; o1.z = v1.z*inv*w1.z; o1.w = v1.w*inv*w1.w;
    float4* outr = (float4*)(out + (size_t)row * DMODEL);
    outr[tid] = o0; outr[tid + 256] = o1;
}

// ---------------- TF32 GEMM (NT): C[M,N] = A[M,K] @ W[N,K]^T ------------------
// 128x256x32 block tile, 8 warps (2m x 4n), warp tile 64x64.
// Double-buffered smem with register prefetch; perm k-layout -> LDS.64 frags.
#define BM 128
#define BN 256
#define BK 32
#define GST 40   // smem row stride (words): frag LDS.64 banks 20g+t4 mod 32, conflict-free
#define GEMM_SMEM_BYTES (2*(BM+BN)*GST*4)

__global__ void __launch_bounds__(256) tgemm_nt(
    const float* __restrict__ A, const float* __restrict__ W,
    const float* __restrict__ bias, const float* __restrict__ res,
    const float* __restrict__ gate, float* __restrict__ C,
    int M, int N, int K, int transC)
{
    extern __shared__ uint32_t smbuf[];
    int tid = threadIdx.x;
    int m0 = blockIdx.y * BM, n0 = blockIdx.x * BN;
    int lane = tid & 31, wid = tid >> 5;
    int warp_m = wid >> 2;     // 0..1 (64 rows)
    int warp_n = wid & 3;      // 0..3 (64 cols)
    int g = lane >> 2, t4 = lane & 3;

    float acc[4][8][4];
    #pragma unroll
    for (int mt = 0; mt < 4; mt++)
        #pragma unroll
        for (int nt = 0; nt < 8; nt++)
            #pragma unroll
            for (int e = 0; e < 4; e++) acc[mt][nt][e] = 0.f;

    const float* Abase = A + (size_t)m0 * K;
    const float* Wbase = W + (size_t)n0 * K;

    float4 pa[4], pb[8];

    auto loadRegs = [&](int k0) {
        #pragma unroll
        for (int i = 0; i < 4; i++) {
            int u = tid + i * 256;
            pa[i] = *(const float4*)(Abase + (size_t)(u >> 3) * K + k0 + ((u & 7) << 2));
        }
        #pragma unroll
        for (int i = 0; i < 8; i++) {
            int u = tid + i * 256;
            pb[i] = *(const float4*)(Wbase + (size_t)(u >> 3) * K + k0 + ((u & 7) << 2));
        }
    };
    auto storeTile = [&](uint32_t* buf) {
        uint32_t* Sa = buf;
        uint32_t* Sb = buf + BM * GST;
        #pragma unroll
        for (int i = 0; i < 4; i++) {
            int u = tid + i * 256;
            int row = u >> 3, kq = (u & 7) << 2;
            int cb = ((kq >> 3) << 3) | ((kq >> 2) & 1);
            Sa[row*GST + cb + 0] = f2tf32(pa[i].x);
            Sa[row*GST + cb + 2] = f2tf32(pa[i].y);
            Sa[row*GST + cb + 4] = f2tf32(pa[i].z);
            Sa[row*GST + cb + 6] = f2tf32(pa[i].w);
        }
        #pragma unroll
        for (int i = 0; i < 8; i++) {
            int u = tid + i * 256;
            int row = u >> 3, kq = (u & 7) << 2;
            int cb = ((kq >> 3) << 3) | ((kq >> 2) & 1);
            Sb[row*GST + cb + 0] = f2tf32(pb[i].x);
            Sb[row*GST + cb + 2] = f2tf32(pb[i].y);
            Sb[row*GST + cb + 4] = f2tf32(pb[i].z);
            Sb[row*GST + cb + 6] = f2tf32(pb[i].w);
        }
    };
    auto mmaTile = [&](const uint32_t* buf) {
        const uint32_t* Sa = buf;
        const uint32_t* Sb = buf + BM * GST;
        #pragma unroll
        for (int kk = 0; kk < 4; kk++) {
            uint2 av0[4], av1[4], bv[8];
            #pragma unroll
            for (int mt = 0; mt < 4; mt++) {
                int r = warp_m * 64 + mt * 16 + g;
                av0[mt] = *(const uint2*)&Sa[r*GST + kk*8 + t4*2];
                av1[mt] = *(const uint2*)&Sa[(r+8)*GST + kk*8 + t4*2];
            }
            #pragma unroll
            for (int nt = 0; nt < 8; nt++) {
                int cn = warp_n * 64 + nt * 8 + g;
                bv[nt] = *(const uint2*)&Sb[cn*GST + kk*8 + t4*2];
            }
            #pragma unroll
            for (int mt = 0; mt < 4; mt++)
                #pragma unroll
                for (int nt = 0; nt < 8; nt++)
                    mma_tf32(acc[mt][nt], av0[mt].x, av1[mt].x, av0[mt].y, av1[mt].y,
                             bv[nt].x, bv[nt].y);
        }
    };

    int nIter = K / BK;
    loadRegs(0);
    storeTile(smbuf);
    __syncthreads();

    for (int it = 0; it < nIter; ++it) {
        uint32_t* cur = smbuf + (it & 1) * ((BM+BN)*GST);
        uint32_t* nxt = smbuf + ((it+1) & 1) * ((BM+BN)*GST);
        bool hasNext = (it + 1 < nIter);
        if (hasNext) loadRegs((it + 1) * BK);
        mmaTile(cur);
        if (hasNext) storeTile(nxt);
        __syncthreads();
    }

    // epilogue
    #pragma unroll
    for (int mt = 0; mt < 4; mt++) {
        int r0 = m0 + warp_m * 64 + mt * 16 + g;
        #pragma unroll
        for (int nt = 0; nt < 8; nt++) {
            int cl = n0 + warp_n * 64 + nt * 8 + t4 * 2;
            #pragma unroll
            for (int half = 0; half < 2; half++) {
                int r = r0 + half * 8;
                float v0 = acc[mt][nt][half*2 + 0];
                float v1 = acc[mt][nt][half*2 + 1];
                if (bias) { v0 += bias[cl]; v1 += bias[cl + 1]; }
                if (transC) {
                    C[(size_t)cl * M + r]       = v0;
                    C[(size_t)(cl + 1) * M + r] = v1;
                } else {
                    size_t idx = (size_t)r * N + cl;
                    if (gate) {
                        float g0 = gate[idx], g1 = gate[idx + 1];
                        v0 *= g0 / (1.f + __expf(-g0));
                        v1 *= g1 / (1.f + __expf(-g1));
                    }
                    if (res) { v0 += res[idx]; v1 += res[idx + 1]; }
                    float2 p; p.x = v0; p.y = v1;
                    *(float2*)(C + idx) = p;
                }
            }
        }
    }
}

// ---------------- Flash attention (causal, GQA rep=4), tf32 MMA ----------------
// 64 q-rows per block, 64-k tiles, online softmax. V consumed transposed (g_vt).
#define AQST 136   // 128 + 8 pad (words)
#define AVST 72    // 64 + 8 pad
#define ASST 65
#define OFF_Q  0
#define OFF_K  (64*AQST)
#define OFF_VT (OFF_K + 64*AQST)
#define OFF_SS (OFF_VT + 128*AVST)
#define OFF_PS (OFF_SS + 64*ASST)
#define OFF_ST (OFF_PS + 64*AVST)
#define ATT_SMEM_BYTES ((OFF_ST + 192) * 4)

__global__ void __launch_bounds__(256) flash_attn_mma(
    const float* __restrict__ Q, const float* __restrict__ Kb,
    const float* __restrict__ Vt, float* __restrict__ O)
{
    extern __shared__ uint32_t sm[];
    uint32_t* Qs = sm + OFF_Q;
    uint32_t* Ks = sm + OFF_K;
    uint32_t* Vs = sm + OFF_VT;
    float*    Ss = (float*)(sm + OFF_SS);
    uint32_t* Ps = sm + OFF_PS;
    float*    ms = (float*)(sm + OFF_ST);
    float*    ls = ms + 64;
    float*    cs = ls + 64;

    int qt = blockIdx.x, bh = blockIdx.y;
    int b = bh >> 4, h = bh & 15, kvh = h & 3;
    int q0 = qt * 64;
    int tid = threadIdx.x;
    int lane = tid & 31, wid = tid >> 5;
    int g = lane >> 2, t4 = lane & 3;
    int wm = wid >> 1;       // 0..3 : 16 rows
    int wn = wid & 1;        // 0..1 : 32 cols (S) / 64 cols (PV)
    const float scale = 0.08838834764831845f;  // 1/sqrt(128)

    // load Q tile (tf32, perm, scale folded)
    for (int u = tid; u < 64*32; u += 256) {
        int r = u >> 5, c4 = (u & 31) << 2;
        float4 qv = *(const float4*)(Q + (size_t)(b*SEQ + q0 + r) * DMODEL + h*HD + c4);
        int cb = ((c4 >> 3) << 3) | ((c4 >> 2) & 1);
        Qs[r*AQST + cb + 0] = f2tf32(qv.x * scale);
        Qs[r*AQST + cb + 2] = f2tf32(qv.y * scale);
        Qs[r*AQST + cb + 4] = f2tf32(qv.z * scale);
        Qs[r*AQST + cb + 6] = f2tf32(qv.w * scale);
    }
    if (tid < 64) { ms[tid] = -INFINITY; ls[tid] = 0.f; }

    float co[8][4];
    #pragma unroll
    for (int nt = 0; nt < 8; nt++)
        #pragma unroll
        for (int e = 0; e < 4; e++) co[nt][e] = 0.f;

    for (int kt = 0; kt <= qt; kt++) {
        int k0 = kt * 64;
        __syncthreads();   // prior iter done with Ks/Vs/Ps; Q ready on iter 0
        for (int u = tid; u < 64*32; u += 256) {
            int r = u >> 5, c4 = (u & 31) << 2;
            float4 kv = *(const float4*)(Kb + (size_t)(b*SEQ + k0 + r) * KD + kvh*HD + c4);
            int cb = ((c4 >> 3) << 3) | ((c4 >> 2) & 1);
            Ks[r*AQST + cb + 0] = f2tf32(kv.x);
            Ks[r*AQST + cb + 2] = f2tf32(kv.y);
            Ks[r*AQST + cb + 4] = f2tf32(kv.z);
            Ks[r*AQST + cb + 6] = f2tf32(kv.w);
        }
        for (int u = tid; u < 128*16; u += 256) {
            int d = u >> 4, s4 = (u & 15) << 2;
            float4 vv = *(const float4*)(Vt + (size_t)(kvh*HD + d) * MROWS + b*SEQ + k0 + s4);
            int cb = ((s4 >> 3) << 3) | ((s4 >> 2) & 1);
            Vs[d*AVST + cb + 0] = f2tf32(vv.x);
            Vs[d*AVST + cb + 2] = f2tf32(vv.y);
            Vs[d*AVST + cb + 4] = f2tf32(vv.z);
            Vs[d*AVST + cb + 6] = f2tf32(vv.w);
        }
        __syncthreads();

        // S = Q K^T  (warp: 16 rows x 32 cols)
        float cscore[4][4];
        #pragma unroll
        for (int nt = 0; nt < 4; nt++)
            #pragma unroll
            for (int e = 0; e < 4; e++) cscore[nt][e] = 0.f;
        #pragma unroll
        for (int kk = 0; kk < 16; kk++) {
            int r = wm * 16 + g;
            uint2 a0v = *(const uint2*)&Qs[r*AQST + kk*8 + t4*2];
            uint2 a1v = *(const uint2*)&Qs[(r+8)*AQST + kk*8 + t4*2];
            #pragma unroll
            for (int nt = 0; nt < 4; nt++) {
                int cn = wn * 32 + nt * 8 + g;
                uint2 bv = *(const uint2*)&Ks[cn*AQST + kk*8 + t4*2];
                mma_tf32(cscore[nt], a0v.x, a1v.x, a0v.y, a1v.y, bv.x, bv.y);
            }
        }
        #pragma unroll
        for (int nt = 0; nt < 4; nt++) {
            int rr = wm * 16 + g;
            int cc = wn * 32 + nt * 8 + t4 * 2;
            Ss[rr*ASST + cc]       = cscore[nt][0];
            Ss[rr*ASST + cc + 1]   = cscore[nt][1];
            Ss[(rr+8)*ASST + cc]   = cscore[nt][2];
            Ss[(rr+8)*ASST + cc+1] = cscore[nt][3];
        }
        __syncthreads();

        // online softmax; emit P in tf32-perm layout
        if (tid < 64) {
            int r = tid;
            int cmax = (kt == qt) ? (r + 1) : 64;
            float mprev = ms[r], mx = mprev;
            for (int c = 0; c < cmax; c++) mx = fmaxf(mx, Ss[r*ASST + c]);
            float corr = __expf(mprev - mx);
            float sum = 0.f;
            for (int c = 0; c < 64; c++) {
                float p = (c < cmax) ? __expf(Ss[r*ASST + c] - mx) : 0.f;
                int cb = ((c >> 3) << 3) | ((c & 3) << 1) | ((c >> 2) & 1);
                Ps[r*AVST + cb] = f2tf32(p);
                sum += p;
            }
            ls[r] = ls[r] * corr + sum;
            ms[r] = mx;
            cs[r] = corr;
        }
        __syncthreads();

        // rescale accumulators, then O += P V  (warp: 16 rows x 64 cols)
        float c0 = cs[wm*16 + g], c1 = cs[wm*16 + 8 + g];
        #pragma unroll
        for (int nt = 0; nt < 8; nt++) {
            co[nt][0] *= c0; co[nt][1] *= c0;
            co[nt][2] *= c1; co[nt][3] *= c1;
        }
        #pragma unroll
        for (int kk = 0; kk < 8; kk++) {
            int r = wm * 16 + g;
            uint2 a0v = *(const uint2*)&Ps[r*AVST + kk*8 + t4*2];
            uint2 a1v = *(const uint2*)&Ps[(r+8)*AVST + kk*8 + t4*2];
            #pragma unroll
            for (int nt = 0; nt < 8; nt++) {
                int cn = wn * 64 + nt * 8 + g;
                uint2 bv = *(const uint2*)&Vs[cn*AVST + kk*8 + t4*2];
                mma_tf32(co[nt], a0v.x, a1v.x, a0v.y, a1v.y, bv.x, bv.y);
            }
        }
    }

    int r0 = wm * 16 + g;
    float inv0 = 1.f / ls[r0];
    float inv1 = 1.f / ls[r0 + 8];
    #pragma unroll
    for (int nt = 0; nt < 8; nt++) {
        int cc = h*HD + wn * 64 + nt * 8 + t4 * 2;
        float2 p0; p0.x = co[nt][0]*inv0; p0.y = co[nt][1]*inv0;
        float2 p1; p1.x = co[nt][2]*inv1; p1.y = co[nt][3]*inv1;
        *(float2*)(O + (size_t)(b*SEQ + q0 + r0) * DMODEL + cc)     = p0;
        *(float2*)(O + (size_t)(b*SEQ + q0 + r0 + 8) * DMODEL + cc) = p1;
    }
}

// ---------------- host launcher ----------------
extern "C" void kernel_launch(void* const* d_in, const int* in_sizes, int n_in,
                              void* d_out, int out_size)
{
    const float* x      = (const float*)d_in[0];
    const float* ln1_w  = (const float*)d_in[1];
    const float* q_w    = (const float*)d_in[2];
    const float* q_b    = (const float*)d_in[3];
    const float* k_w    = (const float*)d_in[4];
    const float* k_b    = (const float*)d_in[5];
    const float* v_w    = (const float*)d_in[6];
    const float* v_b    = (const float*)d_in[7];
    const float* o_w    = (const float*)d_in[8];
    const float* ln2_w  = (const float*)d_in[9];
    const float* gate_w = (const float*)d_in[10];
    const float* up_w   = (const float*)d_in[11];
    const float* down_w = (const float*)d_in[12];
    float* out = (float*)d_out;

    float *h, *q, *k, *vt, *attn, *x1, *h2, *gate, *act;
    cudaGetSymbolAddress((void**)&h,    g_h);
    cudaGetSymbolAddress((void**)&q,    g_q);
    cudaGetSymbolAddress((void**)&k,    g_k);
    cudaGetSymbolAddress((void**)&vt,   g_vt);
    cudaGetSymbolAddress((void**)&attn, g_attn);
    cudaGetSymbolAddress((void**)&x1,   g_x1);
    cudaGetSymbolAddress((void**)&h2,   g_h2);
    cudaGetSymbolAddress((void**)&gate, g_gate);
    cudaGetSymbolAddress((void**)&act,  g_act);

    cudaFuncSetAttribute(tgemm_nt,
                         cudaFuncAttributeMaxDynamicSharedMemorySize, GEMM_SMEM_BYTES);
    cudaFuncSetAttribute(flash_attn_mma,
                         cudaFuncAttributeMaxDynamicSharedMemorySize, ATT_SMEM_BYTES);

    // 1) h = rmsnorm(x)
    rmsnorm_kernel<<<MROWS, 256>>>(x, ln1_w, h);

    // 2) projections
    tgemm_nt<<<dim3(DMODEL/BN, MROWS/BM), 256, GEMM_SMEM_BYTES>>>(
        h, q_w, q_b, nullptr, nullptr, q, MROWS, DMODEL, DMODEL, 0);
    tgemm_nt<<<dim3(KD/BN, MROWS/BM), 256, GEMM_SMEM_BYTES>>>(
        h, k_w, k_b, nullptr, nullptr, k, MROWS, KD, DMODEL, 0);
    tgemm_nt<<<dim3(KD/BN, MROWS/BM), 256, GEMM_SMEM_BYTES>>>(
        h, v_w, v_b, nullptr, nullptr, vt, MROWS, KD, DMODEL, 1);   // transposed out

    // 3) attention
    flash_attn_mma<<<dim3(SEQ/64, BATCH*NH), 256, ATT_SMEM_BYTES>>>(q, k, vt, attn);

    // 4) x1 = x + attn @ o_w^T
    tgemm_nt<<<dim3(DMODEL/BN, MROWS/BM), 256, GEMM_SMEM_BYTES>>>(
        attn, o_w, nullptr, x, nullptr, x1, MROWS, DMODEL, DMODEL, 0);

    // 5) h2 = rmsnorm(x1)
    rmsnorm_kernel<<<MROWS, 256>>>(x1, ln2_w, h2);

    // 6) SwiGLU
    tgemm_nt<<<dim3(FF/BN, MROWS/BM), 256, GEMM_SMEM_BYTES>>>(
        h2, gate_w, nullptr, nullptr, nullptr, gate, MROWS, FF, DMODEL, 0);
    tgemm_nt<<<dim3(FF/BN, MROWS/BM), 256, GEMM_SMEM_BYTES>>>(
        h2, up_w, nullptr, nullptr, gate, act, MROWS, FF, DMODEL, 0);

    // 7) out = x1 + act @ down_w^T
    tgemm_nt<<<dim3(DMODEL/BN, MROWS/BM), 256, GEMM_SMEM_BYTES>>>(
        act, down_w, nullptr, x1, nullptr, out, MROWS, DMODEL, FF, 0);
}

// round 11
// speedup vs baseline: 6.1653x; 2.6188x over previous
#include <cuda_runtime.h>
#include <cuda_fp16.h>
#include <math.h>
#include <stdint.h>

// Problem constants
#define BATCH 2
#define SEQ   2048
#define DMODEL 2048
#define FF    5632
#define NH    16
#define NKVH  4
#define HD    128
#define KD    (NKVH*HD)      // 512
#define MROWS (BATCH*SEQ)    // 4096

// ---------------- scratch (device globals) ----------------
// half weights (pre-converted each call)
__device__ __half hw_q [DMODEL*DMODEL];
__device__ __half hw_k [KD*DMODEL];
__device__ __half hw_v [KD*DMODEL];
__device__ __half hw_o [DMODEL*DMODEL];
__device__ __half hw_g [FF*DMODEL];
__device__ __half hw_u [FF*DMODEL];
__device__ __half hw_d [DMODEL*FF];
// activations
__device__ __half g_h   [MROWS*DMODEL];
__device__ __half g_q   [MROWS*DMODEL];
__device__ __half g_k   [MROWS*KD];
__device__ __half g_vt  [KD*MROWS];       // V transposed [kv_dim][row]
__device__ __half g_attn[MROWS*DMODEL];
__device__ float  g_x1  [MROWS*DMODEL];
__device__ __half g_h2  [MROWS*DMODEL];
__device__ float  g_gate[MROWS*FF];
__device__ __half g_act [MROWS*FF];

// ---------------- helpers ----------------
__device__ __forceinline__ void cp16(uint32_t s, const void* g) {
    asm volatile("cp.async.cg.shared.global [%0], [%1], 16;\n" :: "r"(s), "l"(g));
}
__device__ __forceinline__ void cp_commit() {
    asm volatile("cp.async.commit_group;\n" ::: "memory");
}
__device__ __forceinline__ void cp_wait1() {
    asm volatile("cp.async.wait_group 1;\n" ::: "memory");
}
__device__ __forceinline__ void mma_f16(float* c,
    uint32_t a0, uint32_t a1, uint32_t a2, uint32_t a3, uint32_t b0, uint32_t b1)
{
    asm volatile("mma.sync.aligned.m16n8k16.row.col.f32.f16.f16.f32 "
        "{%0,%1,%2,%3}, {%4,%5,%6,%7}, {%8,%9}, {%0,%1,%2,%3};"
        : "+f"(c[0]), "+f"(c[1]), "+f"(c[2]), "+f"(c[3])
        : "r"(a0), "r"(a1), "r"(a2), "r"(a3), "r"(b0), "r"(b1));
}

// ---------------- fp32 -> fp16 convert ----------------
__global__ void __launch_bounds__(256) f2h_kernel(const float* __restrict__ in,
                                                 __half* __restrict__ out, int n4)
{
    int i = blockIdx.x * 256 + threadIdx.x;
    if (i < n4) {
        float4 v = *(const float4*)(in + (size_t)i * 4);
        __half2 h0 = __floats2half2_rn(v.x, v.y);
        __half2 h1 = __floats2half2_rn(v.z, v.w);
        __half2* o = (__half2*)(out + (size_t)i * 4);
        o[0] = h0; o[1] = h1;
    }
}

// ---------------- RMSNorm: fp32 in, fp16 out ----------------
__global__ void __launch_bounds__(256) rmsnorm_h_kernel(
    const float* __restrict__ x, const float* __restrict__ w, __half* __restrict__ out)
{
    int row = blockIdx.x;
    int tid = threadIdx.x;
    const float4* xr = (const float4*)(x + (size_t)row * DMODEL);
    const float4* wr = (const float4*)w;
    float4 v0 = xr[tid];
    float4 v1 = xr[tid + 256];
    float ss = v0.x*v0.x + v0.y*v0.y + v0.z*v0.z + v0.w*v0.w
             + v1.x*v1.x + v1.y*v1.y + v1.z*v1.z + v1.w*v1.w;
    #pragma unroll
    for (int o = 16; o > 0; o >>= 1) ss += __shfl_xor_sync(0xffffffffu, ss, o);
    __shared__ float red[8];
    if ((tid & 31) == 0) red[tid >> 5] = ss;
    __syncthreads();
    float tot = red[0]+red[1]+red[2]+red[3]+red[4]+red[5]+red[6]+red[7];
    float inv = rsqrtf(tot / (float)DMODEL + 1e-6f);
    float4 w0 = wr[tid], w1 = wr[tid + 256];
    __half2* orow = (__half2*)(out + (size_t)row * DMODEL);
    orow[tid*2 + 0]   = __floats2half2_rn(v0.x*inv*w0.x, v0.y*inv*w0.y);
    orow[tid*2 + 1]   = __floats2half2_rn(v0.z*inv*w0.z, v0.w*inv*w0.w);
    orow[(tid+256)*2]   = __floats2half2_rn(v1.x*inv*w1.x, v1.y*inv*w1.y);
    orow[(tid+256)*2+1] = __floats2half2_rn(v1.z*inv*w1.z, v1.w*inv*w1.w);
}

// ---------------- fp16 GEMM (NT): C[M,N] = A[M,K] @ W[N,K]^T ------------------
// 128x256x64 block tile, 8 warps (2m x 4n), warp tile 64x64, m16n8k16.
// 3-stage cp.async pipeline; 16B-chunk XOR swizzle -> conflict-free frag LDS.
#define BM 128
#define BN 256
#define BKH 64                      // halfs per k-iter (128 bytes/row)
#define STG_A (BM*128)              // 16384 B
#define STG   ((BM+BN)*128)         // 49152 B
#define NSTAGE 3
#define HGEMM_SMEM (NSTAGE*STG)     // 147456 B

// flags
#define F_OUTHALF 1
#define F_TRANSC  2

__global__ void __launch_bounds__(256, 1) hgemm_nt(
    const __half* __restrict__ A, const __half* __restrict__ W,
    const float* __restrict__ bias, const float* __restrict__ res,
    const float* __restrict__ gatep, void* __restrict__ Cout,
    int M, int N, int K, int flags)
{
    extern __shared__ char smem[];
    uint32_t sbase = (uint32_t)__cvta_generic_to_shared(smem);

    int tid = threadIdx.x;
    int m0 = blockIdx.y * BM, n0 = blockIdx.x * BN;
    int lane = tid & 31, wid = tid >> 5;
    int warp_m = wid >> 2;     // 0..1
    int warp_n = wid & 3;      // 0..3
    int g = lane >> 2, t4 = lane & 3;

    float acc[4][8][4];
    #pragma unroll
    for (int mt = 0; mt < 4; mt++)
        #pragma unroll
        for (int nt = 0; nt < 8; nt++)
            #pragma unroll
            for (int e = 0; e < 4; e++) acc[mt][nt][e] = 0.f;

    const __half* Abase = A + (size_t)m0 * K;
    const __half* Wbase = W + (size_t)n0 * K;

    auto issue = [&](int stage, int k0) {
        uint32_t sa = sbase + stage * STG;
        #pragma unroll
        for (int j = 0; j < 4; j++) {                 // A: 128 rows x 8 chunks
            int u = tid + j * 256;
            int r = u >> 3, c = u & 7;
            cp16(sa + r*128 + ((c ^ (r & 7)) << 4),
                 Abase + (size_t)r * K + k0 + c * 8);
        }
        uint32_t sb = sa + STG_A;
        #pragma unroll
        for (int j = 0; j < 8; j++) {                 // B: 256 rows x 8 chunks
            int u = tid + j * 256;
            int r = u >> 3, c = u & 7;
            cp16(sb + r*128 + ((c ^ (r & 7)) << 4),
                 Wbase + (size_t)r * K + k0 + c * 8);
        }
    };

    int nIter = K / BKH;
    issue(0, 0); cp_commit();
    issue(1, BKH); cp_commit();

    for (int it = 0; it < nIter; ++it) {
        cp_wait1();
        __syncthreads();
        if (it + 2 < nIter) issue((it + 2) % NSTAGE, (it + 2) * BKH);
        cp_commit();

        const char* sa = smem + (it % NSTAGE) * STG;
        const char* sb = sa + STG_A;
        #pragma unroll
        for (int kk = 0; kk < 4; kk++) {
            uint32_t a[4][4];
            #pragma unroll
            for (int mt = 0; mt < 4; mt++) {
                int r0 = warp_m * 64 + mt * 16 + g, r1 = r0 + 8;
                a[mt][0] = *(const uint32_t*)(sa + r0*128 + (((2*kk  ) ^ (r0 & 7)) << 4) + t4*4);
                a[mt][1] = *(const uint32_t*)(sa + r1*128 + (((2*kk  ) ^ (r1 & 7)) << 4) + t4*4);
                a[mt][2] = *(const uint32_t*)(sa + r0*128 + (((2*kk+1) ^ (r0 & 7)) << 4) + t4*4);
                a[mt][3] = *(const uint32_t*)(sa + r1*128 + (((2*kk+1) ^ (r1 & 7)) << 4) + t4*4);
            }
            uint32_t b[8][2];
            #pragma unroll
            for (int nt = 0; nt < 8; nt++) {
                int rb = warp_n * 64 + nt * 8 + g;
                b[nt][0] = *(const uint32_t*)(sb + rb*128 + (((2*kk  ) ^ (rb & 7)) << 4) + t4*4);
                b[nt][1] = *(const uint32_t*)(sb + rb*128 + (((2*kk+1) ^ (rb & 7)) << 4) + t4*4);
            }
            #pragma unroll
            for (int mt = 0; mt < 4; mt++)
                #pragma unroll
                for (int nt = 0; nt < 8; nt++)
                    mma_f16(acc[mt][nt], a[mt][0], a[mt][1], a[mt][2], a[mt][3],
                            b[nt][0], b[nt][1]);
        }
        __syncthreads();
    }

    // epilogue
    bool outHalf = flags & F_OUTHALF;
    bool transC  = flags & F_TRANSC;
    #pragma unroll
    for (int mt = 0; mt < 4; mt++) {
        int r0 = m0 + warp_m * 64 + mt * 16 + g;
        #pragma unroll
        for (int nt = 0; nt < 8; nt++) {
            int cl = n0 + warp_n * 64 + nt * 8 + t4 * 2;
            #pragma unroll
            for (int half = 0; half < 2; half++) {
                int r = r0 + half * 8;
                float v0 = acc[mt][nt][half*2 + 0];
                float v1 = acc[mt][nt][half*2 + 1];
                if (bias) { v0 += bias[cl]; v1 += bias[cl + 1]; }
                if (transC) {
                    __half* Ch = (__half*)Cout;
                    Ch[(size_t)cl * M + r]       = __float2half_rn(v0);
                    Ch[(size_t)(cl + 1) * M + r] = __float2half_rn(v1);
                } else {
                    size_t idx = (size_t)r * N + cl;
                    if (gatep) {
                        float g0 = gatep[idx], g1 = gatep[idx + 1];
                        v0 *= g0 / (1.f + __expf(-g0));
                        v1 *= g1 / (1.f + __expf(-g1));
                    }
                    if (res) { v0 += res[idx]; v1 += res[idx + 1]; }
                    if (outHalf) {
                        *(__half2*)((__half*)Cout + idx) = __floats2half2_rn(v0, v1);
                    } else {
                        float2 p; p.x = v0; p.y = v1;
                        *(float2*)((float*)Cout + idx) = p;
                    }
                }
            }
        }
    }
}

// ---------------- Flash attention (causal, GQA rep=4), fp16 MMA ----------------
// 64 q-rows/block, 64-k tiles, online softmax, m16n8k16 for QK^T and PV.
#define AQ_OFF 0                        // Qs: 64 x 256B
#define AK_OFF 16384                    // Ks: 64 x 256B
#define AV_OFF 32768                    // Vs: 128 x 128B
#define AS_OFF 49152                    // Ss: 64 x 65 f32
#define AP_OFF 65792                    // Ps: 64 x 128B
#define AM_OFF 73984                    // ms/ls/cs: 3 x 64 f32
#define ATT_SMEM (AM_OFF + 768)

__global__ void __launch_bounds__(256) flash_attn_h(
    const __half* __restrict__ Q, const __half* __restrict__ Kb,
    const __half* __restrict__ Vt, __half* __restrict__ O)
{
    extern __shared__ char smem[];
    float* Ss  = (float*)(smem + AS_OFF);
    float* ms  = (float*)(smem + AM_OFF);
    float* ls  = ms + 64;
    float* cfs = ls + 64;

    int qt = blockIdx.x, bh = blockIdx.y;
    int b = bh >> 4, h = bh & 15, kvh = h & 3;
    int q0 = qt * 64;
    int tid = threadIdx.x;
    int lane = tid & 31, wid = tid >> 5;
    int g = lane >> 2, t4 = lane & 3;
    int wm = wid >> 1;       // 0..3 : 16 rows
    int wn = wid & 1;        // 0..1
    const float scale = 0.08838834764831845f;

    // load Q tile: 64 rows x 128 halfs (16 chunks of 16B), xor swizzle on low 3 bits
    for (int u = tid; u < 64 * 16; u += 256) {
        int r = u >> 4, c = u & 15;
        uint4 v = *(const uint4*)(Q + (size_t)(b*SEQ + q0 + r) * DMODEL + h*HD + c*8);
        *(uint4*)(smem + AQ_OFF + r*256 + ((c ^ (r & 7)) << 4)) = v;
    }
    if (tid < 64) { ms[tid] = -INFINITY; ls[tid] = 0.f; }

    float co[8][4];
    #pragma unroll
    for (int nt = 0; nt < 8; nt++)
        #pragma unroll
        for (int e = 0; e < 4; e++) co[nt][e] = 0.f;

    for (int kt = 0; kt <= qt; kt++) {
        int k0 = kt * 64;
        __syncthreads();    // prior iter done with Ks/Vs/Ps
        for (int u = tid; u < 64 * 16; u += 256) {   // K: 64 rows x 16 chunks
            int r = u >> 4, c = u & 15;
            uint4 v = *(const uint4*)(Kb + (size_t)(b*SEQ + k0 + r) * KD + kvh*HD + c*8);
            *(uint4*)(smem + AK_OFF + r*256 + ((c ^ (r & 7)) << 4)) = v;
        }
        for (int u = tid; u < 128 * 8; u += 256) {   // V^T: 128 rows x 8 chunks
            int d = u >> 3, c = u & 7;
            uint4 v = *(const uint4*)(Vt + (size_t)(kvh*HD + d) * MROWS + b*SEQ + k0 + c*8);
            *(uint4*)(smem + AV_OFF + d*128 + ((c ^ (d & 7)) << 4)) = v;
        }
        __syncthreads();

        // S = Q K^T : warp computes 16 rows x 32 cols, k-steps of 16 over HD
        float sc[4][4];
        #pragma unroll
        for (int nt = 0; nt < 4; nt++)
            #pragma unroll
            for (int e = 0; e < 4; e++) sc[nt][e] = 0.f;
        #pragma unroll
        for (int kk = 0; kk < 8; kk++) {
            int r0 = wm * 16 + g, r1 = r0 + 8;
            uint32_t a0 = *(const uint32_t*)(smem + AQ_OFF + r0*256 + (((2*kk  ) ^ (r0 & 7)) << 4) + t4*4);
            uint32_t a1 = *(const uint32_t*)(smem + AQ_OFF + r1*256 + (((2*kk  ) ^ (r1 & 7)) << 4) + t4*4);
            uint32_t a2 = *(const uint32_t*)(smem + AQ_OFF + r0*256 + (((2*kk+1) ^ (r0 & 7)) << 4) + t4*4);
            uint32_t a3 = *(const uint32_t*)(smem + AQ_OFF + r1*256 + (((2*kk+1) ^ (r1 & 7)) << 4) + t4*4);
            #pragma unroll
            for (int nt = 0; nt < 4; nt++) {
                int rb = wn * 32 + nt * 8 + g;
                uint32_t b0 = *(const uint32_t*)(smem + AK_OFF + rb*256 + (((2*kk  ) ^ (rb & 7)) << 4) + t4*4);
                uint32_t b1 = *(const uint32_t*)(smem + AK_OFF + rb*256 + (((2*kk+1) ^ (rb & 7)) << 4) + t4*4);
                mma_f16(sc[nt], a0, a1, a2, a3, b0, b1);
            }
        }
        {
            int rr = wm * 16 + g;
            #pragma unroll
            for (int nt = 0; nt < 4; nt++) {
                int cc = wn * 32 + nt * 8 + t4 * 2;
                Ss[rr*65 + cc]       = sc[nt][0] * scale;
                Ss[rr*65 + cc + 1]   = sc[nt][1] * scale;
                Ss[(rr+8)*65 + cc]   = sc[nt][2] * scale;
                Ss[(rr+8)*65 + cc+1] = sc[nt][3] * scale;
            }
        }
        __syncthreads();

        // online softmax: 2 threads per row
        if (tid < 128) {
            int r = tid >> 1, hf = tid & 1;
            int cmax = (kt == qt) ? (r + 1) : 64;
            int lo = hf * 32;
            int hi = cmax < lo + 32 ? cmax : lo + 32;
            float mx = -INFINITY;
            for (int c = lo; c < hi; c++) mx = fmaxf(mx, Ss[r*65 + c]);
            mx = fmaxf(mx, __shfl_xor_sync(0xffffffffu, mx, 1));
            float mprev = ms[r];
            float mxn = fmaxf(mx, mprev);
            float sum = 0.f;
            for (int c = lo; c < lo + 32; c += 2) {
                float p0 = (c     < cmax) ? __expf(Ss[r*65 + c]     - mxn) : 0.f;
                float p1 = (c + 1 < cmax) ? __expf(Ss[r*65 + c + 1] - mxn) : 0.f;
                sum += p0 + p1;
                int u = c >> 1;  // half2 index
                *(__half2*)(smem + AP_OFF + r*128 + (((u >> 2) ^ (r & 7)) << 4) + (u & 3)*4)
                    = __floats2half2_rn(p0, p1);
            }
            sum += __shfl_xor_sync(0xffffffffu, sum, 1);
            if (hf == 0) {
                float corr = __expf(mprev - mxn);
                ls[r] = ls[r] * corr + sum;
                ms[r] = mxn;
                cfs[r] = corr;
            }
        }
        __syncthreads();

        // rescale, then O += P V : warp 16 rows x 64 cols, k-steps of 16 over 64
        float c0 = cfs[wm*16 + g], c1 = cfs[wm*16 + 8 + g];
        #pragma unroll
        for (int nt = 0; nt < 8; nt++) {
            co[nt][0] *= c0; co[nt][1] *= c0;
            co[nt][2] *= c1; co[nt][3] *= c1;
        }
        #pragma unroll
        for (int kk = 0; kk < 4; kk++) {
            int r0 = wm * 16 + g, r1 = r0 + 8;
            uint32_t a0 = *(const uint32_t*)(smem + AP_OFF + r0*128 + (((2*kk  ) ^ (r0 & 7)) << 4) + t4*4);
            uint32_t a1 = *(const uint32_t*)(smem + AP_OFF + r1*128 + (((2*kk  ) ^ (r1 & 7)) << 4) + t4*4);
            uint32_t a2 = *(const uint32_t*)(smem + AP_OFF + r0*128 + (((2*kk+1) ^ (r0 & 7)) << 4) + t4*4);
            uint32_t a3 = *(const uint32_t*)(smem + AP_OFF + r1*128 + (((2*kk+1) ^ (r1 & 7)) << 4) + t4*4);
            #pragma unroll
            for (int nt = 0; nt < 8; nt++) {
                int d = wn * 64 + nt * 8 + g;
                uint32_t b0 = *(const uint32_t*)(smem + AV_OFF + d*128 + (((2*kk  ) ^ (d & 7)) << 4) + t4*4);
                uint32_t b1 = *(const uint32_t*)(smem + AV_OFF + d*128 + (((2*kk+1) ^ (d & 7)) << 4) + t4*4);
                mma_f16(co[nt], a0, a1, a2, a3, b0, b1);
            }
        }
    }

    int r0 = wm * 16 + g;
    float inv0 = 1.f / ls[r0];
    float inv1 = 1.f / ls[r0 + 8];
    #pragma unroll
    for (int nt = 0; nt < 8; nt++) {
        int cc = h*HD + wn * 64 + nt * 8 + t4 * 2;
        *(__half2*)(O + (size_t)(b*SEQ + q0 + r0) * DMODEL + cc)
            = __floats2half2_rn(co[nt][0]*inv0, co[nt][1]*inv0);
        *(__half2*)(O + (size_t)(b*SEQ + q0 + r0 + 8) * DMODEL + cc)
            = __floats2half2_rn(co[nt][2]*inv1, co[nt][3]*inv1);
    }
}

// ---------------- host launcher ----------------
extern "C" void kernel_launch(void* const* d_in, const int* in_sizes, int n_in,
                              void* d_out, int out_size)
{
    const float* x      = (const float*)d_in[0];
    const float* ln1_w  = (const float*)d_in[1];
    const float* q_w    = (const float*)d_in[2];
    const float* q_b    = (const float*)d_in[3];
    const float* k_w    = (const float*)d_in[4];
    const float* k_b    = (const float*)d_in[5];
    const float* v_w    = (const float*)d_in[6];
    const float* v_b    = (const float*)d_in[7];
    const float* o_w    = (const float*)d_in[8];
    const float* ln2_w  = (const float*)d_in[9];
    const float* gate_w = (const float*)d_in[10];
    const float* up_w   = (const float*)d_in[11];
    const float* down_w = (const float*)d_in[12];
    float* out = (float*)d_out;

    __half *wq, *wk, *wv, *wo, *wg, *wu, *wd;
    __half *h, *q, *k, *vt, *attn, *h2, *act;
    float *x1, *gate;
    cudaGetSymbolAddress((void**)&wq, hw_q);
    cudaGetSymbolAddress((void**)&wk, hw_k);
    cudaGetSymbolAddress((void**)&wv, hw_v);
    cudaGetSymbolAddress((void**)&wo, hw_o);
    cudaGetSymbolAddress((void**)&wg, hw_g);
    cudaGetSymbolAddress((void**)&wu, hw_u);
    cudaGetSymbolAddress((void**)&wd, hw_d);
    cudaGetSymbolAddress((void**)&h,    g_h);
    cudaGetSymbolAddress((void**)&q,    g_q);
    cudaGetSymbolAddress((void**)&k,    g_k);
    cudaGetSymbolAddress((void**)&vt,   g_vt);
    cudaGetSymbolAddress((void**)&attn, g_attn);
    cudaGetSymbolAddress((void**)&x1,   g_x1);
    cudaGetSymbolAddress((void**)&h2,   g_h2);
    cudaGetSymbolAddress((void**)&gate, g_gate);
    cudaGetSymbolAddress((void**)&act,  g_act);

    cudaFuncSetAttribute(hgemm_nt,
                         cudaFuncAttributeMaxDynamicSharedMemorySize, HGEMM_SMEM);
    cudaFuncSetAttribute(flash_attn_h,
                         cudaFuncAttributeMaxDynamicSharedMemorySize, ATT_SMEM);

    // 0) weights -> fp16
    auto cvt = [&](const float* src, __half* dst, int n) {
        int n4 = n / 4;
        f2h_kernel<<<(n4 + 255) / 256, 256>>>(src, dst, n4);
    };
    cvt(q_w,    wq, DMODEL*DMODEL);
    cvt(k_w,    wk, KD*DMODEL);
    cvt(v_w,    wv, KD*DMODEL);
    cvt(o_w,    wo, DMODEL*DMODEL);
    cvt(gate_w, wg, FF*DMODEL);
    cvt(up_w,   wu, FF*DMODEL);
    cvt(down_w, wd, DMODEL*FF);

    // 1) h = rmsnorm(x) -> fp16
    rmsnorm_h_kernel<<<MROWS, 256>>>(x, ln1_w, h);

    // 2) projections (fp16 MMA)
    hgemm_nt<<<dim3(DMODEL/BN, MROWS/BM), 256, HGEMM_SMEM>>>(
        h, wq, q_b, nullptr, nullptr, q, MROWS, DMODEL, DMODEL, F_OUTHALF);
    hgemm_nt<<<dim3(KD/BN, MROWS/BM), 256, HGEMM_SMEM>>>(
        h, wk, k_b, nullptr, nullptr, k, MROWS, KD, DMODEL, F_OUTHALF);
    hgemm_nt<<<dim3(KD/BN, MROWS/BM), 256, HGEMM_SMEM>>>(
        h, wv, v_b, nullptr, nullptr, vt, MROWS, KD, DMODEL, F_TRANSC);

    // 3) attention
    flash_attn_h<<<dim3(SEQ/64, BATCH*NH), 256, ATT_SMEM>>>(q, k, vt, attn);

    // 4) x1 = x + attn @ o_w^T  (fp32 out)
    hgemm_nt<<<dim3(DMODEL/BN, MROWS/BM), 256, HGEMM_SMEM>>>(
        attn, wo, nullptr, x, nullptr, x1, MROWS, DMODEL, DMODEL, 0);

    // 5) h2 = rmsnorm(x1) -> fp16
    rmsnorm_h_kernel<<<MROWS, 256>>>(x1, ln2_w, h2);

    // 6) SwiGLU
    hgemm_nt<<<dim3(FF/BN, MROWS/BM), 256, HGEMM_SMEM>>>(
        h2, wg, nullptr, nullptr, nullptr, gate, MROWS, FF, DMODEL, 0);
    hgemm_nt<<<dim3(FF/BN, MROWS/BM), 256, HGEMM_SMEM>>>(
        h2, wu, nullptr, nullptr, gate, act, MROWS, FF, DMODEL, F_OUTHALF);

    // 7) out = x1 + act @ down_w^T  (fp32 out)
    hgemm_nt<<<dim3(DMODEL/BN, MROWS/BM), 256, HGEMM_SMEM>>>(
        act, wd, nullptr, x1, nullptr, out, MROWS, DMODEL, FF, 0);
}

// round 12
// speedup vs baseline: 6.4812x; 1.0512x over previous
#include <cuda_runtime.h>
#include <cuda_fp16.h>
#include <math.h>
#include <stdint.h>

// Problem constants
#define BATCH 2
#define SEQ   2048
#define DMODEL 2048
#define FF    5632
#define NH    16
#define NKVH  4
#define HD    128
#define KD    (NKVH*HD)      // 512
#define MROWS (BATCH*SEQ)    // 4096

// ---------------- scratch (device globals) ----------------
__device__ __half hw_q [DMODEL*DMODEL];
__device__ __half hw_k [KD*DMODEL];
__device__ __half hw_v [KD*DMODEL];
__device__ __half hw_o [DMODEL*DMODEL];
__device__ __half hw_g [FF*DMODEL];
__device__ __half hw_u [FF*DMODEL];
__device__ __half hw_d [DMODEL*FF];
__device__ __half g_h   [MROWS*DMODEL];
__device__ __half g_q   [MROWS*DMODEL];
__device__ __half g_k   [MROWS*KD];
__device__ __half g_vt  [KD*MROWS];       // V transposed [kv_dim][row]
__device__ __half g_attn[MROWS*DMODEL];
__device__ float  g_x1  [MROWS*DMODEL];
__device__ __half g_h2  [MROWS*DMODEL];
__device__ __half g_gate[MROWS*FF];       // now fp16
__device__ __half g_act [MROWS*FF];

// ---------------- helpers ----------------
__device__ __forceinline__ void cp16(uint32_t s, const void* g) {
    asm volatile("cp.async.cg.shared.global [%0], [%1], 16;\n" :: "r"(s), "l"(g));
}
__device__ __forceinline__ void cp_commit() {
    asm volatile("cp.async.commit_group;\n" ::: "memory");
}
__device__ __forceinline__ void cp_wait2() {
    asm volatile("cp.async.wait_group 2;\n" ::: "memory");
}
__device__ __forceinline__ void mma_f16(float* c,
    uint32_t a0, uint32_t a1, uint32_t a2, uint32_t a3, uint32_t b0, uint32_t b1)
{
    asm volatile("mma.sync.aligned.m16n8k16.row.col.f32.f16.f16.f32 "
        "{%0,%1,%2,%3}, {%4,%5,%6,%7}, {%8,%9}, {%0,%1,%2,%3};"
        : "+f"(c[0]), "+f"(c[1]), "+f"(c[2]), "+f"(c[3])
        : "r"(a0), "r"(a1), "r"(a2), "r"(a3), "r"(b0), "r"(b1));
}
__device__ __forceinline__ void ldsm4(uint32_t& r0, uint32_t& r1, uint32_t& r2, uint32_t& r3,
                                      uint32_t addr)
{
    asm volatile("ldmatrix.sync.aligned.m8n8.x4.shared.b16 {%0,%1,%2,%3}, [%4];"
        : "=r"(r0), "=r"(r1), "=r"(r2), "=r"(r3) : "r"(addr));
}

// ---------------- fp32 -> fp16 convert ----------------
__global__ void __launch_bounds__(256) f2h_kernel(const float* __restrict__ in,
                                                 __half* __restrict__ out, int n4)
{
    int i = blockIdx.x * 256 + threadIdx.x;
    if (i < n4) {
        float4 v = *(const float4*)(in + (size_t)i * 4);
        __half2 h0 = __floats2half2_rn(v.x, v.y);
        __half2 h1 = __floats2half2_rn(v.z, v.w);
        __half2* o = (__half2*)(out + (size_t)i * 4);
        o[0] = h0; o[1] = h1;
    }
}

// ---------------- RMSNorm: fp32 in, fp16 out ----------------
__global__ void __launch_bounds__(256) rmsnorm_h_kernel(
    const float* __restrict__ x, const float* __restrict__ w, __half* __restrict__ out)
{
    int row = blockIdx.x;
    int tid = threadIdx.x;
    const float4* xr = (const float4*)(x + (size_t)row * DMODEL);
    const float4* wr = (const float4*)w;
    float4 v0 = xr[tid];
    float4 v1 = xr[tid + 256];
    float ss = v0.x*v0.x + v0.y*v0.y + v0.z*v0.z + v0.w*v0.w
             + v1.x*v1.x + v1.y*v1.y + v1.z*v1.z + v1.w*v1.w;
    #pragma unroll
    for (int o = 16; o > 0; o >>= 1) ss += __shfl_xor_sync(0xffffffffu, ss, o);
    __shared__ float red[8];
    if ((tid & 31) == 0) red[tid >> 5] = ss;
    __syncthreads();
    float tot = red[0]+red[1]+red[2]+red[3]+red[4]+red[5]+red[6]+red[7];
    float inv = rsqrtf(tot / (float)DMODEL + 1e-6f);
    float4 w0 = wr[tid], w1 = wr[tid + 256];
    __half2* orow = (__half2*)(out + (size_t)row * DMODEL);
    orow[tid*2 + 0]   = __floats2half2_rn(v0.x*inv*w0.x, v0.y*inv*w0.y);
    orow[tid*2 + 1]   = __floats2half2_rn(v0.z*inv*w0.z, v0.w*inv*w0.w);
    orow[(tid+256)*2]   = __floats2half2_rn(v1.x*inv*w1.x, v1.y*inv*w1.y);
    orow[(tid+256)*2+1] = __floats2half2_rn(v1.z*inv*w1.z, v1.w*inv*w1.w);
}

// ---------------- fp16 GEMM (NT): C[M,N] = A[M,K] @ W[N,K]^T ------------------
// 128x256x64 block tile, 8 warps (2m x 4n), warp tile 64x64, m16n8k16.
// 4-stage cp.async pipeline; XOR-swizzled layout; ldmatrix.x4 fragment loads.
#define BM 128
#define BN 256
#define BKH 64                      // halfs per k-iter (128 bytes/row)
#define STG_A (BM*128)              // 16384 B
#define STG   ((BM+BN)*128)         // 49152 B
#define NSTAGE 4
#define HGEMM_SMEM (NSTAGE*STG)     // 196608 B

// flags
#define F_OUTHALF 1
#define F_TRANSC  2

__global__ void __launch_bounds__(256, 1) hgemm_nt(
    const __half* __restrict__ A, const __half* __restrict__ W,
    const float* __restrict__ bias, const float* __restrict__ res,
    const __half* __restrict__ gatep, void* __restrict__ Cout,
    int M, int N, int K, int flags)
{
    extern __shared__ char smem[];
    uint32_t sbase = (uint32_t)__cvta_generic_to_shared(smem);

    int tid = threadIdx.x;
    int m0 = blockIdx.y * BM, n0 = blockIdx.x * BN;
    int lane = tid & 31, wid = tid >> 5;
    int warp_m = wid >> 2;     // 0..1
    int warp_n = wid & 3;      // 0..3
    int g = lane >> 2, t4 = lane & 3;
    int lm = lane >> 3, lr = lane & 7;   // ldmatrix decomposition

    float acc[4][8][4];
    #pragma unroll
    for (int mt = 0; mt < 4; mt++)
        #pragma unroll
        for (int nt = 0; nt < 8; nt++)
            #pragma unroll
            for (int e = 0; e < 4; e++) acc[mt][nt][e] = 0.f;

    // ldmatrix per-lane row bases
    // A (mt): matrices (rows+0..7 chunk 2kk), (rows+8.. chunk 2kk), (rows chunk 2kk+1), (rows+8 chunk 2kk+1)
    //   lane role: row = base + (lm&1)*8 + lr, chunk_hi = lm>>1
    int aHi = lm >> 1;
    uint32_t aRow128[4]; int aR7[4];
    #pragma unroll
    for (int mt = 0; mt < 4; mt++) {
        int r = warp_m * 64 + mt * 16 + (lm & 1) * 8 + lr;
        aRow128[mt] = (uint32_t)r * 128; aR7[mt] = r & 7;
    }
    // B (pair p -> nt=2p,2p+1): row = base + (lm>>1)*8 + lr, chunk_lo = lm&1
    int bLo = lm & 1;
    uint32_t bRow128[4]; int bR7[4];
    #pragma unroll
    for (int p = 0; p < 4; p++) {
        int r = warp_n * 64 + p * 16 + (lm >> 1) * 8 + lr;
        bRow128[p] = (uint32_t)r * 128; bR7[p] = r & 7;
    }

    const __half* Abase = A + (size_t)m0 * K;
    const __half* Wbase = W + (size_t)n0 * K;

    auto issue = [&](int stage, int k0) {
        uint32_t sa = sbase + stage * STG;
        #pragma unroll
        for (int j = 0; j < 4; j++) {                 // A: 128 rows x 8 chunks
            int u = tid + j * 256;
            int r = u >> 3, c = u & 7;
            cp16(sa + r*128 + ((c ^ (r & 7)) << 4),
                 Abase + (size_t)r * K + k0 + c * 8);
        }
        uint32_t sb = sa + STG_A;
        #pragma unroll
        for (int j = 0; j < 8; j++) {                 // B: 256 rows x 8 chunks
            int u = tid + j * 256;
            int r = u >> 3, c = u & 7;
            cp16(sb + r*128 + ((c ^ (r & 7)) << 4),
                 Wbase + (size_t)r * K + k0 + c * 8);
        }
    };

    int nIter = K / BKH;
    issue(0, 0); cp_commit();
    issue(1, BKH); cp_commit();
    issue(2, 2*BKH); cp_commit();

    for (int it = 0; it < nIter; ++it) {
        cp_wait2();
        __syncthreads();
        if (it + 3 < nIter) issue((it + 3) % NSTAGE, (it + 3) * BKH);
        cp_commit();

        uint32_t saU = sbase + (it % NSTAGE) * STG;
        uint32_t sbU = saU + STG_A;
        #pragma unroll
        for (int kk = 0; kk < 4; kk++) {
            uint32_t a[4][4], b[8][2];
            #pragma unroll
            for (int mt = 0; mt < 4; mt++) {
                uint32_t addr = saU + aRow128[mt] + ((uint32_t)((2*kk + aHi) ^ aR7[mt]) << 4);
                ldsm4(a[mt][0], a[mt][1], a[mt][2], a[mt][3], addr);
            }
            #pragma unroll
            for (int p = 0; p < 4; p++) {
                uint32_t addr = sbU + bRow128[p] + ((uint32_t)((2*kk + bLo) ^ bR7[p]) << 4);
                ldsm4(b[2*p][0], b[2*p][1], b[2*p+1][0], b[2*p+1][1], addr);
            }
            #pragma unroll
            for (int mt = 0; mt < 4; mt++)
                #pragma unroll
                for (int nt = 0; nt < 8; nt++)
                    mma_f16(acc[mt][nt], a[mt][0], a[mt][1], a[mt][2], a[mt][3],
                            b[nt][0], b[nt][1]);
        }
        __syncthreads();
    }

    // epilogue
    bool outHalf = flags & F_OUTHALF;
    bool transC  = flags & F_TRANSC;
    #pragma unroll
    for (int mt = 0; mt < 4; mt++) {
        int r0 = m0 + warp_m * 64 + mt * 16 + g;
        #pragma unroll
        for (int nt = 0; nt < 8; nt++) {
            int cl = n0 + warp_n * 64 + nt * 8 + t4 * 2;
            #pragma unroll
            for (int half = 0; half < 2; half++) {
                int r = r0 + half * 8;
                float v0 = acc[mt][nt][half*2 + 0];
                float v1 = acc[mt][nt][half*2 + 1];
                if (bias) { v0 += bias[cl]; v1 += bias[cl + 1]; }
                if (transC) {
                    __half* Ch = (__half*)Cout;
                    Ch[(size_t)cl * M + r]       = __float2half_rn(v0);
                    Ch[(size_t)(cl + 1) * M + r] = __float2half_rn(v1);
                } else {
                    size_t idx = (size_t)r * N + cl;
                    if (gatep) {
                        __half2 gh = *(const __half2*)(gatep + idx);
                        float g0 = __half2float(__low2half(gh));
                        float g1 = __half2float(__high2half(gh));
                        v0 *= g0 / (1.f + __expf(-g0));
                        v1 *= g1 / (1.f + __expf(-g1));
                    }
                    if (res) { v0 += res[idx]; v1 += res[idx + 1]; }
                    if (outHalf) {
                        *(__half2*)((__half*)Cout + idx) = __floats2half2_rn(v0, v1);
                    } else {
                        float2 p; p.x = v0; p.y = v1;
                        *(float2*)((float*)Cout + idx) = p;
                    }
                }
            }
        }
    }
}

// ---------------- Flash attention (causal, GQA rep=4), fp16 MMA ----------------
#define AQ_OFF 0                        // Qs: 64 x 256B
#define AK_OFF 16384                    // Ks: 64 x 256B
#define AV_OFF 32768                    // Vs: 128 x 128B
#define AS_OFF 49152                    // Ss: 64 x 65 f32
#define AP_OFF 65792                    // Ps: 64 x 128B
#define AM_OFF 73984                    // ms/ls/cs: 3 x 64 f32
#define ATT_SMEM (AM_OFF + 768)

__global__ void __launch_bounds__(256) flash_attn_h(
    const __half* __restrict__ Q, const __half* __restrict__ Kb,
    const __half* __restrict__ Vt, __half* __restrict__ O)
{
    extern __shared__ char smem[];
    float* Ss  = (float*)(smem + AS_OFF);
    float* ms  = (float*)(smem + AM_OFF);
    float* ls  = ms + 64;
    float* cfs = ls + 64;

    int qt = blockIdx.x, bh = blockIdx.y;
    int b = bh >> 4, h = bh & 15, kvh = h & 3;
    int q0 = qt * 64;
    int tid = threadIdx.x;
    int lane = tid & 31, wid = tid >> 5;
    int g = lane >> 2, t4 = lane & 3;
    int wm = wid >> 1;       // 0..3 : 16 rows
    int wn = wid & 1;        // 0..1
    const float scale = 0.08838834764831845f;

    for (int u = tid; u < 64 * 16; u += 256) {
        int r = u >> 4, c = u & 15;
        uint4 v = *(const uint4*)(Q + (size_t)(b*SEQ + q0 + r) * DMODEL + h*HD + c*8);
        *(uint4*)(smem + AQ_OFF + r*256 + ((c ^ (r & 7)) << 4)) = v;
    }
    if (tid < 64) { ms[tid] = -INFINITY; ls[tid] = 0.f; }

    float co[8][4];
    #pragma unroll
    for (int nt = 0; nt < 8; nt++)
        #pragma unroll
        for (int e = 0; e < 4; e++) co[nt][e] = 0.f;

    for (int kt = 0; kt <= qt; kt++) {
        int k0 = kt * 64;
        __syncthreads();
        for (int u = tid; u < 64 * 16; u += 256) {
            int r = u >> 4, c = u & 15;
            uint4 v = *(const uint4*)(Kb + (size_t)(b*SEQ + k0 + r) * KD + kvh*HD + c*8);
            *(uint4*)(smem + AK_OFF + r*256 + ((c ^ (r & 7)) << 4)) = v;
        }
        for (int u = tid; u < 128 * 8; u += 256) {
            int d = u >> 3, c = u & 7;
            uint4 v = *(const uint4*)(Vt + (size_t)(kvh*HD + d) * MROWS + b*SEQ + k0 + c*8);
            *(uint4*)(smem + AV_OFF + d*128 + ((c ^ (d & 7)) << 4)) = v;
        }
        __syncthreads();

        float sc[4][4];
        #pragma unroll
        for (int nt = 0; nt < 4; nt++)
            #pragma unroll
            for (int e = 0; e < 4; e++) sc[nt][e] = 0.f;
        #pragma unroll
        for (int kk = 0; kk < 8; kk++) {
            int r0 = wm * 16 + g, r1 = r0 + 8;
            uint32_t a0 = *(const uint32_t*)(smem + AQ_OFF + r0*256 + (((2*kk  ) ^ (r0 & 7)) << 4) + t4*4);
            uint32_t a1 = *(const uint32_t*)(smem + AQ_OFF + r1*256 + (((2*kk  ) ^ (r1 & 7)) << 4) + t4*4);
            uint32_t a2 = *(const uint32_t*)(smem + AQ_OFF + r0*256 + (((2*kk+1) ^ (r0 & 7)) << 4) + t4*4);
            uint32_t a3 = *(const uint32_t*)(smem + AQ_OFF + r1*256 + (((2*kk+1) ^ (r1 & 7)) << 4) + t4*4);
            #pragma unroll
            for (int nt = 0; nt < 4; nt++) {
                int rb = wn * 32 + nt * 8 + g;
                uint32_t b0 = *(const uint32_t*)(smem + AK_OFF + rb*256 + (((2*kk  ) ^ (rb & 7)) << 4) + t4*4);
                uint32_t b1 = *(const uint32_t*)(smem + AK_OFF + rb*256 + (((2*kk+1) ^ (rb & 7)) << 4) + t4*4);
                mma_f16(sc[nt], a0, a1, a2, a3, b0, b1);
            }
        }
        {
            int rr = wm * 16 + g;
            #pragma unroll
            for (int nt = 0; nt < 4; nt++) {
                int cc = wn * 32 + nt * 8 + t4 * 2;
                Ss[rr*65 + cc]       = sc[nt][0] * scale;
                Ss[rr*65 + cc + 1]   = sc[nt][1] * scale;
                Ss[(rr+8)*65 + cc]   = sc[nt][2] * scale;
                Ss[(rr+8)*65 + cc+1] = sc[nt][3] * scale;
            }
        }
        __syncthreads();

        if (tid < 128) {
            int r = tid >> 1, hf = tid & 1;
            int cmax = (kt == qt) ? (r + 1) : 64;
            int lo = hf * 32;
            int hi = cmax < lo + 32 ? cmax : lo + 32;
            float mx = -INFINITY;
            for (int c = lo; c < hi; c++) mx = fmaxf(mx, Ss[r*65 + c]);
            mx = fmaxf(mx, __shfl_xor_sync(0xffffffffu, mx, 1));
            float mprev = ms[r];
            float mxn = fmaxf(mx, mprev);
            float sum = 0.f;
            for (int c = lo; c < lo + 32; c += 2) {
                float p0 = (c     < cmax) ? __expf(Ss[r*65 + c]     - mxn) : 0.f;
                float p1 = (c + 1 < cmax) ? __expf(Ss[r*65 + c + 1] - mxn) : 0.f;
                sum += p0 + p1;
                int u = c >> 1;
                *(__half2*)(smem + AP_OFF + r*128 + (((u >> 2) ^ (r & 7)) << 4) + (u & 3)*4)
                    = __floats2half2_rn(p0, p1);
            }
            sum += __shfl_xor_sync(0xffffffffu, sum, 1);
            if (hf == 0) {
                float corr = __expf(mprev - mxn);
                ls[r] = ls[r] * corr + sum;
                ms[r] = mxn;
                cfs[r] = corr;
            }
        }
        __syncthreads();

        float c0 = cfs[wm*16 + g], c1 = cfs[wm*16 + 8 + g];
        #pragma unroll
        for (int nt = 0; nt < 8; nt++) {
            co[nt][0] *= c0; co[nt][1] *= c0;
            co[nt][2] *= c1; co[nt][3] *= c1;
        }
        #pragma unroll
        for (int kk = 0; kk < 4; kk++) {
            int r0 = wm * 16 + g, r1 = r0 + 8;
            uint32_t a0 = *(const uint32_t*)(smem + AP_OFF + r0*128 + (((2*kk  ) ^ (r0 & 7)) << 4) + t4*4);
            uint32_t a1 = *(const uint32_t*)(smem + AP_OFF + r1*128 + (((2*kk  ) ^ (r1 & 7)) << 4) + t4*4);
            uint32_t a2 = *(const uint32_t*)(smem + AP_OFF + r0*128 + (((2*kk+1) ^ (r0 & 7)) << 4) + t4*4);
            uint32_t a3 = *(const uint32_t*)(smem + AP_OFF + r1*128 + (((2*kk+1) ^ (r1 & 7)) << 4) + t4*4);
            #pragma unroll
            for (int nt = 0; nt < 8; nt++) {
                int d = wn * 64 + nt * 8 + g;
                uint32_t b0 = *(const uint32_t*)(smem + AV_OFF + d*128 + (((2*kk  ) ^ (d & 7)) << 4) + t4*4);
                uint32_t b1 = *(const uint32_t*)(smem + AV_OFF + d*128 + (((2*kk+1) ^ (d & 7)) << 4) + t4*4);
                mma_f16(co[nt], a0, a1, a2, a3, b0, b1);
            }
        }
    }

    int r0 = wm * 16 + g;
    float inv0 = 1.f / ls[r0];
    float inv1 = 1.f / ls[r0 + 8];
    #pragma unroll
    for (int nt = 0; nt < 8; nt++) {
        int cc = h*HD + wn * 64 + nt * 8 + t4 * 2;
        *(__half2*)(O + (size_t)(b*SEQ + q0 + r0) * DMODEL + cc)
            = __floats2half2_rn(co[nt][0]*inv0, co[nt][1]*inv0);
        *(__half2*)(O + (size_t)(b*SEQ + q0 + r0 + 8) * DMODEL + cc)
            = __floats2half2_rn(co[nt][2]*inv1, co[nt][3]*inv1);
    }
}

// ---------------- host launcher ----------------
extern "C" void kernel_launch(void* const* d_in, const int* in_sizes, int n_in,
                              void* d_out, int out_size)
{
    const float* x      = (const float*)d_in[0];
    const float* ln1_w  = (const float*)d_in[1];
    const float* q_w    = (const float*)d_in[2];
    const float* q_b    = (const float*)d_in[3];
    const float* k_w    = (const float*)d_in[4];
    const float* k_b    = (const float*)d_in[5];
    const float* v_w    = (const float*)d_in[6];
    const float* v_b    = (const float*)d_in[7];
    const float* o_w    = (const float*)d_in[8];
    const float* ln2_w  = (const float*)d_in[9];
    const float* gate_w = (const float*)d_in[10];
    const float* up_w   = (const float*)d_in[11];
    const float* down_w = (const float*)d_in[12];
    float* out = (float*)d_out;

    __half *wq, *wk, *wv, *wo, *wg, *wu, *wd;
    __half *h, *q, *k, *vt, *attn, *h2, *act, *gate;
    float *x1;
    cudaGetSymbolAddress((void**)&wq, hw_q);
    cudaGetSymbolAddress((void**)&wk, hw_k);
    cudaGetSymbolAddress((void**)&wv, hw_v);
    cudaGetSymbolAddress((void**)&wo, hw_o);
    cudaGetSymbolAddress((void**)&wg, hw_g);
    cudaGetSymbolAddress((void**)&wu, hw_u);
    cudaGetSymbolAddress((void**)&wd, hw_d);
    cudaGetSymbolAddress((void**)&h,    g_h);
    cudaGetSymbolAddress((void**)&q,    g_q);
    cudaGetSymbolAddress((void**)&k,    g_k);
    cudaGetSymbolAddress((void**)&vt,   g_vt);
    cudaGetSymbolAddress((void**)&attn, g_attn);
    cudaGetSymbolAddress((void**)&x1,   g_x1);
    cudaGetSymbolAddress((void**)&h2,   g_h2);
    cudaGetSymbolAddress((void**)&gate, g_gate);
    cudaGetSymbolAddress((void**)&act,  g_act);

    cudaFuncSetAttribute(hgemm_nt,
                         cudaFuncAttributeMaxDynamicSharedMemorySize, HGEMM_SMEM);
    cudaFuncSetAttribute(flash_attn_h,
                         cudaFuncAttributeMaxDynamicSharedMemorySize, ATT_SMEM);

    // 0) weights -> fp16
    auto cvt = [&](const float* src, __half* dst, int n) {
        int n4 = n / 4;
        f2h_kernel<<<(n4 + 255) / 256, 256>>>(src, dst, n4);
    };
    cvt(q_w,    wq, DMODEL*DMODEL);
    cvt(k_w,    wk, KD*DMODEL);
    cvt(v_w,    wv, KD*DMODEL);
    cvt(o_w,    wo, DMODEL*DMODEL);
    cvt(gate_w, wg, FF*DMODEL);
    cvt(up_w,   wu, FF*DMODEL);
    cvt(down_w, wd, DMODEL*FF);

    // 1) h = rmsnorm(x) -> fp16
    rmsnorm_h_kernel<<<MROWS, 256>>>(x, ln1_w, h);

    // 2) projections
    hgemm_nt<<<dim3(DMODEL/BN, MROWS/BM), 256, HGEMM_SMEM>>>(
        h, wq, q_b, nullptr, nullptr, q, MROWS, DMODEL, DMODEL, F_OUTHALF);
    hgemm_nt<<<dim3(KD/BN, MROWS/BM), 256, HGEMM_SMEM>>>(
        h, wk, k_b, nullptr, nullptr, k, MROWS, KD, DMODEL, F_OUTHALF);
    hgemm_nt<<<dim3(KD/BN, MROWS/BM), 256, HGEMM_SMEM>>>(
        h, wv, v_b, nullptr, nullptr, vt, MROWS, KD, DMODEL, F_TRANSC);

    // 3) attention
    flash_attn_h<<<dim3(SEQ/64, BATCH*NH), 256, ATT_SMEM>>>(q, k, vt, attn);

    // 4) x1 = x + attn @ o_w^T  (fp32 out)
    hgemm_nt<<<dim3(DMODEL/BN, MROWS/BM), 256, HGEMM_SMEM>>>(
        attn, wo, nullptr, x, nullptr, x1, MROWS, DMODEL, DMODEL, 0);

    // 5) h2 = rmsnorm(x1) -> fp16
    rmsnorm_h_kernel<<<MROWS, 256>>>(x1, ln2_w, h2);

    // 6) SwiGLU (gate fp16 intermediate)
    hgemm_nt<<<dim3(FF/BN, MROWS/BM), 256, HGEMM_SMEM>>>(
        h2, wg, nullptr, nullptr, nullptr, gate, MROWS, FF, DMODEL, F_OUTHALF);
    hgemm_nt<<<dim3(FF/BN, MROWS/BM), 256, HGEMM_SMEM>>>(
        h2, wu, nullptr, nullptr, gate, act, MROWS, FF, DMODEL, F_OUTHALF);

    // 7) out = x1 + act @ down_w^T  (fp32 out)
    hgemm_nt<<<dim3(DMODEL/BN, MROWS/BM), 256, HGEMM_SMEM>>>(
        act, wd, nullptr, x1, nullptr, out, MROWS, DMODEL, FF, 0);
}